// round 11
// baseline (speedup 1.0000x reference)
#include <cuda_runtime.h>
#include <cstdint>

#define N_NODES 10000
#define N_EDGES 640000
#define TE 256
#define TN 512

typedef uint32_t u32;

// ---------------- device scratch ----------------
__device__ float g_hagg[N_NODES * 128];
__device__ float g_cagg4[N_NODES * 4];
__device__ float g_P[N_NODES * 128];
__device__ float g_Q[N_NODES * 128];
__device__ float g_zb[128];
__device__ uint4 g_Bf2[8 * 512];         // We2 3-term
__device__ uint2 g_Bf3[8 * 512];         // Wc1 hi-only
__device__ uint4 g_Bfn1[16 * 512];       // Wn1 3-term (K=256)
__device__ uint4 g_Bfn2[8 * 512];        // Wn2 3-term
__device__ int   g_bins[N_NODES];        // histogram -> offsets (running)
__device__ int   g_srow[N_EDGES];        // row, sorted by row
__device__ int   g_scol[N_EDGES];        // col, same permutation

__device__ __forceinline__ float silu_f(float x) { return x / (1.0f + __expf(-x)); }

__device__ __forceinline__ u32 bf16x2_rn(float x0, float x1) {
    u32 r; asm("cvt.rn.bf16x2.f32 %0, %1, %2;" : "=r"(r) : "f"(x1), "f"(x0)); return r;
}
__device__ __forceinline__ u32 bf16x2_lo(float x0, float x1, u32 h) {
    float h0 = __uint_as_float(h << 16);
    float h1 = __uint_as_float(h & 0xffff0000u);
    return bf16x2_rn(x0 - h0, x1 - h1);
}
__device__ __forceinline__ u32 smem_u32(const void* p) {
    u32 a;
    asm("{ .reg .u64 t; cvta.to.shared.u64 t, %1; cvt.u32.u64 %0, t; }"
        : "=r"(a) : "l"(p));
    return a;
}
__device__ __forceinline__ void ldsm_x4(u32* r, u32 addr) {
    asm volatile("ldmatrix.sync.aligned.m8n8.x4.shared.b16 {%0,%1,%2,%3}, [%4];"
        : "=r"(r[0]), "=r"(r[1]), "=r"(r[2]), "=r"(r[3]) : "r"(addr));
}
__device__ __forceinline__ void red_v4(float* p, float4 v) {
    asm volatile("red.global.add.v4.f32 [%0], {%1,%2,%3,%4};"
        :: "l"(p), "f"(v.x), "f"(v.y), "f"(v.z), "f"(v.w) : "memory");
}
__device__ __forceinline__ void red_v2(float* p, float a, float b) {
    asm volatile("red.global.add.v2.f32 [%0], {%1,%2};"
        :: "l"(p), "f"(a), "f"(b) : "memory");
}

#define MMA_BF16(d, a0, a1, a2, a3, b0, b1)                                 \
    asm volatile(                                                           \
        "mma.sync.aligned.m16n8k16.row.col.f32.bf16.bf16.f32 "              \
        "{%0,%1,%2,%3},{%4,%5,%6,%7},{%8,%9},{%0,%1,%2,%3};"                \
        : "+f"((d)[0]), "+f"((d)[1]), "+f"((d)[2]), "+f"((d)[3])            \
        : "r"(a0), "r"(a1), "r"(a2), "r"(a3), "r"(b0), "r"(b1))

// ---------------- prep: weights -> bf16 fragments ----------------
__global__ void prep_kernel(const float* __restrict__ We2,
                            const float* __restrict__ Wc1,
                            const float* __restrict__ Wn1,
                            const float* __restrict__ Wn2)
{
    int i = blockIdx.x * blockDim.x + threadIdx.x;
    const float* W; int idx, mode;
    if (i < 4096)        { W = We2; idx = i;         mode = 0; }
    else if (i < 8192)   { W = Wc1; idx = i - 4096;  mode = 1; }
    else if (i < 16384)  { W = Wn1; idx = i - 8192;  mode = 2; }
    else if (i < 20480)  { W = Wn2; idx = i - 16384; mode = 3; }
    else return;

    int c = idx >> 9, rem = idx & 511;
    int t = rem >> 5, l = rem & 31;
    int g = l >> 2, tig = l & 3;
    int n = t * 8 + g;
    int k0 = c * 16 + 2 * tig;
    float w0 = W[(k0    ) * 128 + n];
    float w1 = W[(k0 + 1) * 128 + n];
    float w2 = W[(k0 + 8) * 128 + n];
    float w3 = W[(k0 + 9) * 128 + n];
    u32 bh01 = bf16x2_rn(w0, w1), bh23 = bf16x2_rn(w2, w3);
    u32 bl01 = bf16x2_lo(w0, w1, bh01), bl23 = bf16x2_lo(w2, w3, bh23);
    if (mode == 0)      g_Bf2[idx]  = make_uint4(bh01, bh23, bl01, bl23);
    else if (mode == 1) g_Bf3[idx]  = make_uint2(bh01, bh23);
    else if (mode == 2) g_Bfn1[idx] = make_uint4(bh01, bh23, bl01, bl23);
    else                g_Bfn2[idx] = make_uint4(bh01, bh23, bl01, bl23);
}

__global__ void zero_kernel()
{
    int i = blockIdx.x * blockDim.x + threadIdx.x;
    int st = gridDim.x * blockDim.x;
    for (int k = i; k < N_NODES * 128; k += st) g_hagg[k] = 0.0f;
    for (int k = i; k < N_NODES * 4;   k += st) g_cagg4[k] = 0.0f;
    for (int k = i; k < N_NODES;       k += st) g_bins[k] = 0;
}

// ---------------- counting sort: hist -> scan -> scatter ----------------
__global__ void hist_kernel(const int* __restrict__ ei)
{
    int i = blockIdx.x * blockDim.x + threadIdx.x;
    if (i < N_EDGES) atomicAdd(&g_bins[ei[i]], 1);
}

__global__ void scan_kernel()   // 1 block, 1024 threads, 10 bins/thread
{
    __shared__ int part[1024];
    int t = threadIdx.x;
    int base = t * 10;
    int loc[10]; int sum = 0;
#pragma unroll
    for (int k = 0; k < 10; k++) {
        int b = base + k;
        int v = (b < N_NODES) ? g_bins[b] : 0;
        loc[k] = sum; sum += v;
    }
    part[t] = sum;
    __syncthreads();
    for (int off = 1; off < 1024; off <<= 1) {
        int v = (t >= off) ? part[t - off] : 0;
        __syncthreads();
        part[t] += v;
        __syncthreads();
    }
    int pre = (t == 0) ? 0 : part[t - 1];
#pragma unroll
    for (int k = 0; k < 10; k++) {
        int b = base + k;
        if (b < N_NODES) g_bins[b] = pre + loc[k];
    }
}

__global__ void scatter_kernel(const int* __restrict__ ei)
{
    int i = blockIdx.x * blockDim.x + threadIdx.x;
    if (i >= N_EDGES) return;
    int r = ei[i];
    int pos = atomicAdd(&g_bins[r], 1);
    g_srow[pos] = r;
    g_scol[pos] = ei[N_EDGES + i];
}

// ---------------- scalar fp32 GEMM tile (pre_kernel only) ----------------
template<int K, bool SILU>
__device__ __forceinline__ void gemm_tile(
    const float* __restrict__ sIn, int inStride,
    const float* __restrict__ W, const float* __restrict__ bias,
    float* __restrict__ sOut, int outStride, float* __restrict__ s_w)
{
    const int tx = threadIdx.x & 31;
    const int r0 = (threadIdx.x >> 5) * 4;
    float acc[4][4];
#pragma unroll
    for (int i = 0; i < 4; i++)
#pragma unroll
        for (int c = 0; c < 4; c++) acc[i][c] = 0.0f;

    for (int kc = 0; kc < K; kc += 16) {
        __syncthreads();
        {
            int t = threadIdx.x, r = t >> 5, c = t & 31;
            ((float4*)s_w)[r * 33 + c] = *((const float4*)(W + (size_t)(kc + r) * 128) + c);
        }
        __syncthreads();
#pragma unroll
        for (int kk = 0; kk < 16; kk += 4) {
            float4 av[4];
#pragma unroll
            for (int i = 0; i < 4; i++)
                av[i] = *(const float4*)&sIn[(r0 + i) * inStride + kc + kk];
#pragma unroll
            for (int q = 0; q < 4; q++) {
                float4 w = ((const float4*)s_w)[(kk + q) * 33 + tx];
#pragma unroll
                for (int i = 0; i < 4; i++) {
                    float a = (q == 0) ? av[i].x : (q == 1) ? av[i].y
                              : (q == 2) ? av[i].z : av[i].w;
                    acc[i][0] = fmaf(a, w.x, acc[i][0]);
                    acc[i][1] = fmaf(a, w.y, acc[i][1]);
                    acc[i][2] = fmaf(a, w.z, acc[i][2]);
                    acc[i][3] = fmaf(a, w.w, acc[i][3]);
                }
            }
        }
    }
    float4 b = *((const float4*)bias + tx);
#pragma unroll
    for (int i = 0; i < 4; i++) {
        float4 v;
        v.x = acc[i][0] + b.x; v.y = acc[i][1] + b.y;
        v.z = acc[i][2] + b.z; v.w = acc[i][3] + b.w;
        if (SILU) { v.x = silu_f(v.x); v.y = silu_f(v.y); v.z = silu_f(v.z); v.w = silu_f(v.w); }
        *(float4*)&sOut[(r0 + i) * outStride + tx * 4] = v;
    }
}

// ---------------- pre: P = h@We1_top + be1, Q = h@We1_bot ----------------
#define PRE_SMEM_BYTES ((64*132 + 16*33*4 + 64*132) * 4)
__global__ void __launch_bounds__(TN, 1)
pre_kernel(const float* __restrict__ h, const float* __restrict__ We1,
           const float* __restrict__ be1)
{
    extern __shared__ float smf[];
    float* s_in  = smf;
    float* s_w   = s_in + 64 * 132;
    float* s_out = s_w + 16 * 33 * 4;
    const int tid = threadIdx.x;
    const int n0  = blockIdx.x * 64;

    for (int idx = tid; idx < 64 * 128; idx += TN) {
        int r = idx >> 7, c = idx & 127, n = n0 + r;
        s_in[r * 132 + c] = (n < N_NODES) ? h[(size_t)n * 128 + c] : 0.0f;
    }
    gemm_tile<128, false>(s_in, 132, We1, be1, s_out, 132, s_w);
    __syncthreads();
    for (int idx = tid; idx < 64 * 128; idx += TN) {
        int r = idx >> 7, c = idx & 127, n = n0 + r;
        if (n < N_NODES) g_P[(size_t)n * 128 + c] = s_out[r * 132 + c];
    }
    __syncthreads();
    gemm_tile<128, false>(s_in, 132, We1 + 128 * 128, g_zb, s_out, 132, s_w);
    __syncthreads();
    for (int idx = tid; idx < 64 * 128; idx += TN) {
        int r = idx >> 7, c = idx & 127, n = n0 + r;
        if (n < N_NODES) g_Q[(size_t)n * 128 + c] = s_out[r * 132 + c];
    }
}

// ---------------- bf16 mma cores ----------------
template<int KC>
__device__ __forceinline__ void mma3(
    u32 AhiA, u32 AloA, int SA,
    const uint4* __restrict__ Bf, float acc[2][4][4],
    int m0, int ntb, int lane)
{
    int arow = (m0 + (lane & 15)) * SA + ((lane >> 4) << 2);
    u32 h0 = AhiA + arow * 4, h1 = h0 + 16 * SA * 4;
    u32 l0 = AloA + arow * 4, l1 = l0 + 16 * SA * 4;
#pragma unroll
    for (int c = 0; c < KC; c++) {
        uint4 bf[4];
#pragma unroll
        for (int nt = 0; nt < 4; nt++)
            bf[nt] = __ldg(Bf + (c * 16 + ntb + nt) * 32 + lane);
        u32 ah[2][4], al[2][4];
        ldsm_x4(ah[0], h0 + c * 32);
        ldsm_x4(ah[1], h1 + c * 32);
        ldsm_x4(al[0], l0 + c * 32);
        ldsm_x4(al[1], l1 + c * 32);
#pragma unroll
        for (int nt = 0; nt < 4; nt++) {
#pragma unroll
            for (int mt = 0; mt < 2; mt++) {
                MMA_BF16(acc[mt][nt], ah[mt][0], ah[mt][1], ah[mt][2], ah[mt][3],
                         bf[nt].x, bf[nt].y);
                MMA_BF16(acc[mt][nt], al[mt][0], al[mt][1], al[mt][2], al[mt][3],
                         bf[nt].x, bf[nt].y);
                MMA_BF16(acc[mt][nt], ah[mt][0], ah[mt][1], ah[mt][2], ah[mt][3],
                         bf[nt].z, bf[nt].w);
            }
        }
    }
}

template<int KC>
__device__ __forceinline__ void mma1t(
    u32 AhiA, int SA,
    const uint2* __restrict__ Bf, float acc[2][4][4],
    int m0, int ntb, int lane)
{
    int arow = (m0 + (lane & 15)) * SA + ((lane >> 4) << 2);
    u32 h0 = AhiA + arow * 4, h1 = h0 + 16 * SA * 4;
#pragma unroll
    for (int c = 0; c < KC; c++) {
        uint2 bf[4];
#pragma unroll
        for (int nt = 0; nt < 4; nt++)
            bf[nt] = __ldg(Bf + (c * 16 + ntb + nt) * 32 + lane);
        u32 ah[2][4];
        ldsm_x4(ah[0], h0 + c * 32);
        ldsm_x4(ah[1], h1 + c * 32);
#pragma unroll
        for (int nt = 0; nt < 4; nt++) {
#pragma unroll
            for (int mt = 0; mt < 2; mt++) {
                MMA_BF16(acc[mt][nt], ah[mt][0], ah[mt][1], ah[mt][2], ah[mt][3],
                         bf[nt].x, bf[nt].y);
            }
        }
    }
}

#define ZACC(acc) do { _Pragma("unroll") for (int a_ = 0; a_ < 2; a_++) \
    _Pragma("unroll") for (int b_ = 0; b_ < 4; b_++) \
    _Pragma("unroll") for (int c_ = 0; c_ < 4; c_++) acc[a_][b_][c_] = 0.0f; } while (0)

// ---------------- edge kernel ----------------
#define SH 68
#define OFF_HIDH 0
#define OFF_HIDL 4352
#define OFF_EFH  8704
#define OFF_MISC 13056
#define SMEM_EDGE_U32 (OFF_MISC + 1152)
#define SMEM_EDGE_BYTES (SMEM_EDGE_U32 * 4)

__global__ void __launch_bounds__(TE, 3)
edge_kernel(const float* __restrict__ y,
            const float* __restrict__ w256,
            const float* __restrict__ be2, const float* __restrict__ bc1,
            const float* __restrict__ Wc2)
{
    extern __shared__ u32 smu[];
    u32* hidH = smu + OFF_HIDH;
    u32* hidL = smu + OFF_HIDL;
    u32* efH  = smu + OFF_EFH;
    float* s_w256 = (float*)(smu + OFF_MISC);
    float* s_be2  = s_w256 + 128;
    float* s_bc1  = s_be2 + 128;
    float* s_wc2  = s_bc1 + 128;
    float* s_rad  = s_wc2 + 128;
    float* s_diff = s_rad + 64;
    float* s_part = s_diff + 192;
    int*   s_row  = (int*)(s_part + 256);
    int*   s_col  = s_row + 64;

    const int tid  = threadIdx.x;
    const int lane = tid & 31;
    const int wid  = tid >> 5;
    const int g    = lane >> 2;
    const int tig  = lane & 3;
    const int mw   = wid >> 2;
    const int nw   = wid & 3;
    const int m0   = mw * 32;
    const int ntb  = nw * 4;
    const int e0g  = blockIdx.x * 64;

    const u32 smb   = smem_u32(smu);
    const u32 hidHa = smb + OFF_HIDH * 4;
    const u32 hidLa = smb + OFF_HIDL * 4;
    const u32 efHa  = smb + OFF_EFH * 4;

    if (tid < 64) {
        int r = g_srow[e0g + tid], c = g_scol[e0g + tid];
        s_row[tid] = r; s_col[tid] = c;
        float dx = y[r*3+0]-y[c*3+0], dy = y[r*3+1]-y[c*3+1], dz = y[r*3+2]-y[c*3+2];
        s_diff[tid*3+0] = dx; s_diff[tid*3+1] = dy; s_diff[tid*3+2] = dz;
        s_rad[tid] = dx*dx + dy*dy + dz*dz;
    }
    if (tid < 128) {
        s_w256[tid] = w256[tid];
        s_be2[tid] = be2[tid]; s_bc1[tid] = bc1[tid]; s_wc2[tid] = Wc2[tid];
    }
    __syncthreads();

    // ---- fused former-GEMM1: hid = silu(P[row] + Q[col] + rad*w256) ----
    // rows sorted -> P[row] loads are L1 hits after the first edge
#pragma unroll 2
    for (int t = wid; t < 64; t += 8) {
        int rnode = s_row[t], cnode = s_col[t];
        float4 p = __ldg((const float4*)(g_P + (size_t)rnode * 128) + lane);
        float4 q = __ldg((const float4*)(g_Q + (size_t)cnode * 128) + lane);
        float rad = s_rad[t];
        float4 w = *(const float4*)&s_w256[lane * 4];
        float v0 = silu_f(p.x + q.x + rad * w.x);
        float v1 = silu_f(p.y + q.y + rad * w.y);
        float v2 = silu_f(p.z + q.z + rad * w.z);
        float v3 = silu_f(p.w + q.w + rad * w.w);
        u32 h0 = bf16x2_rn(v0, v1), h1 = bf16x2_rn(v2, v3);
        int o = t * SH + lane * 2;
        *(uint2*)&hidH[o] = make_uint2(h0, h1);
        *(uint2*)&hidL[o] = make_uint2(bf16x2_lo(v0, v1, h0), bf16x2_lo(v2, v3, h1));
    }
    __syncthreads();

    float acc[2][4][4];

    // ---- GEMM2: hid @ We2 (3-term) ----
    ZACC(acc);
    mma3<8>(hidHa, hidLa, SH, g_Bf2, acc, m0, ntb, lane);
    // epilogue: ef bf16 hi -> SMEM; hagg scatter from registers (row-local lines)
#pragma unroll
    for (int mt = 0; mt < 2; mt++) {
        int ra = m0 + mt * 16 + g, rb = ra + 8;
        size_t na = (size_t)s_row[ra] * 128, nb = (size_t)s_row[rb] * 128;
#pragma unroll
        for (int nt = 0; nt < 4; nt++) {
            int col = (ntb + nt) * 8 + 2 * tig;
            int uc  = (ntb + nt) * 4 + tig;
            float b0 = s_be2[col], b1 = s_be2[col + 1];
            float v0 = silu_f(acc[mt][nt][0] + b0), v1 = silu_f(acc[mt][nt][1] + b1);
            float v2 = silu_f(acc[mt][nt][2] + b0), v3 = silu_f(acc[mt][nt][3] + b1);
            efH[ra * SH + uc] = bf16x2_rn(v0, v1);
            efH[rb * SH + uc] = bf16x2_rn(v2, v3);
            red_v2(&g_hagg[na + col], v0, v1);
            red_v2(&g_hagg[nb + col], v2, v3);
        }
    }
    __syncthreads();

    // ---- GEMM3: ef @ Wc1 (1-term, coord path) ----
    ZACC(acc);
    mma1t<8>(efHa, SH, g_Bf3, acc, m0, ntb, lane);
    {
        float p[4] = {0.f, 0.f, 0.f, 0.f};
#pragma unroll
        for (int mt = 0; mt < 2; mt++) {
#pragma unroll
            for (int nt = 0; nt < 4; nt++) {
                int col = (ntb + nt) * 8 + 2 * tig;
                float b0 = s_bc1[col], b1 = s_bc1[col + 1];
                float w0 = s_wc2[col], w1 = s_wc2[col + 1];
                p[mt*2+0] += silu_f(acc[mt][nt][0] + b0) * w0
                           + silu_f(acc[mt][nt][1] + b1) * w1;
                p[mt*2+1] += silu_f(acc[mt][nt][2] + b0) * w0
                           + silu_f(acc[mt][nt][3] + b1) * w1;
            }
        }
#pragma unroll
        for (int i = 0; i < 4; i++) {
            p[i] += __shfl_xor_sync(0xffffffffu, p[i], 1);
            p[i] += __shfl_xor_sync(0xffffffffu, p[i], 2);
        }
        if (tig == 0) {
#pragma unroll
            for (int mt = 0; mt < 2; mt++) {
                s_part[nw * 64 + m0 + mt * 16 + g]     = p[mt*2+0];
                s_part[nw * 64 + m0 + mt * 16 + g + 8] = p[mt*2+1];
            }
        }
    }
    __syncthreads();

    // ---- coord scatter: segmented pre-reduction over sorted rows ----
    if (tid < 64) {
        float s = s_part[tid] + s_part[64 + tid] + s_part[128 + tid] + s_part[192 + tid];
        s_part[tid] = s;   // each thread writes only its own slot
    }
    __syncthreads();
    if (tid < 64) {
        int r = s_row[tid];
        bool first = (tid == 0) || (s_row[tid - 1] != r);
        if (first) {
            float sx = 0.f, sy = 0.f, sz = 0.f, cf = 0.f;
            int j = tid;
            do {
                float s = s_part[j];
                sx += s_diff[j*3+0] * s;
                sy += s_diff[j*3+1] * s;
                sz += s_diff[j*3+2] * s;
                cf += 1.0f;
                j++;
            } while (j < 64 && s_row[j] == r);
            red_v4(&g_cagg4[r * 4], make_float4(sx, sy, sz, cf));
        }
    }
}

// ---------------- node kernel: bf16 mma ----------------
#define SHN 132
#define NOFF_AHI 0
#define NOFF_ALO 8448
#define NOFF_HH  16896
#define NOFF_HL  21248
#define NOFF_MISC 25600
#define SMEM_NODE_U32 (NOFF_MISC + 256)
#define SMEM_NODE_BYTES (SMEM_NODE_U32 * 4)

__global__ void __launch_bounds__(TE, 1)
node_mma_kernel(const float* __restrict__ h, const float* __restrict__ y,
                const float* __restrict__ bn1, const float* __restrict__ bn2,
                float* __restrict__ out_h, float* __restrict__ out_y)
{
    extern __shared__ u32 smu[];
    u32* AhiN = smu + NOFF_AHI;
    u32* AloN = smu + NOFF_ALO;
    u32* hidH = smu + NOFF_HH;
    u32* hidL = smu + NOFF_HL;
    float* s_bn1 = (float*)(smu + NOFF_MISC);
    float* s_bn2 = s_bn1 + 128;

    const int tid  = threadIdx.x;
    const int lane = tid & 31;
    const int wid  = tid >> 5;
    const int g    = lane >> 2;
    const int tig  = lane & 3;
    const int mw   = wid >> 2;
    const int nw   = wid & 3;
    const int m0   = mw * 32;
    const int ntb  = nw * 4;
    const int n0   = blockIdx.x * 64;

    const u32 smb = smem_u32(smu);
    const u32 AhiA = smb + NOFF_AHI * 4;
    const u32 AloA = smb + NOFF_ALO * 4;
    const u32 hHa  = smb + NOFF_HH * 4;
    const u32 hLa  = smb + NOFF_HL * 4;

    if (tid < 128) { s_bn1[tid] = bn1[tid]; s_bn2[tid] = bn2[tid]; }

    for (int t = wid; t < 128; t += 8) {
        int r = t >> 1, half = t & 1, n = n0 + r;
        float4 v = make_float4(0.f, 0.f, 0.f, 0.f);
        if (n < N_NODES) {
            const float* src = half ? (g_hagg + (size_t)n * 128) : (h + (size_t)n * 128);
            v = __ldg((const float4*)src + lane);
        }
        u32 h0 = bf16x2_rn(v.x, v.y), h1 = bf16x2_rn(v.z, v.w);
        int o = r * SHN + half * 64 + lane * 2;
        *(uint2*)&AhiN[o] = make_uint2(h0, h1);
        *(uint2*)&AloN[o] = make_uint2(bf16x2_lo(v.x, v.y, h0), bf16x2_lo(v.z, v.w, h1));
    }
    __syncthreads();

    float acc[2][4][4];

    ZACC(acc);
    mma3<16>(AhiA, AloA, SHN, g_Bfn1, acc, m0, ntb, lane);
#pragma unroll
    for (int mt = 0; mt < 2; mt++) {
        int ra = m0 + mt * 16 + g, rb = ra + 8;
#pragma unroll
        for (int nt = 0; nt < 4; nt++) {
            int col = (ntb + nt) * 8 + 2 * tig;
            int uc  = (ntb + nt) * 4 + tig;
            float b0 = s_bn1[col], b1 = s_bn1[col + 1];
            float v0 = silu_f(acc[mt][nt][0] + b0), v1 = silu_f(acc[mt][nt][1] + b1);
            float v2 = silu_f(acc[mt][nt][2] + b0), v3 = silu_f(acc[mt][nt][3] + b1);
            u32 ha = bf16x2_rn(v0, v1), hb = bf16x2_rn(v2, v3);
            hidH[ra * SH + uc] = ha; hidL[ra * SH + uc] = bf16x2_lo(v0, v1, ha);
            hidH[rb * SH + uc] = hb; hidL[rb * SH + uc] = bf16x2_lo(v2, v3, hb);
        }
    }
    __syncthreads();

    ZACC(acc);
    mma3<8>(hHa, hLa, SH, g_Bfn2, acc, m0, ntb, lane);
#pragma unroll
    for (int mt = 0; mt < 2; mt++) {
        int ra = m0 + mt * 16 + g, rb = ra + 8;
        int na = n0 + ra, nb = n0 + rb;
#pragma unroll
        for (int nt = 0; nt < 4; nt++) {
            int col = (ntb + nt) * 8 + 2 * tig;
            float b0 = s_bn2[col], b1 = s_bn2[col + 1];
            if (na < N_NODES) {
                float2 hh = __ldg((const float2*)(h + (size_t)na * 128 + col));
                *(float2*)&out_h[(size_t)na * 128 + col] =
                    make_float2(acc[mt][nt][0] + b0 + hh.x, acc[mt][nt][1] + b1 + hh.y);
            }
            if (nb < N_NODES) {
                float2 hh = __ldg((const float2*)(h + (size_t)nb * 128 + col));
                *(float2*)&out_h[(size_t)nb * 128 + col] =
                    make_float2(acc[mt][nt][2] + b0 + hh.x, acc[mt][nt][3] + b1 + hh.y);
            }
        }
    }

    if (tid < 64) {
        int n = n0 + tid;
        if (n < N_NODES) {
            float c = g_cagg4[n * 4 + 3]; c = (c < 1.0f) ? 1.0f : c;
            out_y[n*3+0] = y[n*3+0] + g_cagg4[n*4+0] / c;
            out_y[n*3+1] = y[n*3+1] + g_cagg4[n*4+1] / c;
            out_y[n*3+2] = y[n*3+2] + g_cagg4[n*4+2] / c;
        }
    }
}

extern "C" void kernel_launch(void* const* d_in, const int* in_sizes, int n_in,
                              void* d_out, int out_size)
{
    const float* h   = (const float*)d_in[0];
    const float* y   = (const float*)d_in[1];
    const int*   ei  = (const int*)d_in[2];
    const float* We1 = (const float*)d_in[3];
    const float* be1 = (const float*)d_in[4];
    const float* We2 = (const float*)d_in[5];
    const float* be2 = (const float*)d_in[6];
    const float* Wc1 = (const float*)d_in[7];
    const float* bc1 = (const float*)d_in[8];
    const float* Wc2 = (const float*)d_in[9];
    const float* Wn1 = (const float*)d_in[10];
    const float* bn1 = (const float*)d_in[11];
    const float* Wn2 = (const float*)d_in[12];
    const float* bn2 = (const float*)d_in[13];

    float* out_h = (float*)d_out;
    float* out_y = out_h + (size_t)N_NODES * 128;

    cudaFuncSetAttribute(edge_kernel, cudaFuncAttributeMaxDynamicSharedMemorySize,
                         SMEM_EDGE_BYTES);
    cudaFuncSetAttribute(node_mma_kernel, cudaFuncAttributeMaxDynamicSharedMemorySize,
                         SMEM_NODE_BYTES);
    cudaFuncSetAttribute(pre_kernel, cudaFuncAttributeMaxDynamicSharedMemorySize,
                         PRE_SMEM_BYTES);

    zero_kernel<<<512, TE>>>();
    prep_kernel<<<80, 256>>>(We2, Wc1, Wn1, Wn2);
    hist_kernel<<<(N_EDGES + 255) / 256, 256>>>(ei);
    scan_kernel<<<1, 1024>>>();
    scatter_kernel<<<(N_EDGES + 255) / 256, 256>>>(ei);
    pre_kernel<<<(N_NODES + 63) / 64, TN, PRE_SMEM_BYTES>>>(h, We1, be1);

    edge_kernel<<<N_EDGES / 64, TE, SMEM_EDGE_BYTES>>>(
        y, We1 + 256 * 128, be2, bc1, Wc2);

    node_mma_kernel<<<(N_NODES + 63) / 64, TE, SMEM_NODE_BYTES>>>(
        h, y, bn1, bn2, out_h, out_y);
}

// round 12
// speedup vs baseline: 1.3116x; 1.3116x over previous
#include <cuda_runtime.h>
#include <cstdint>

#define N_NODES 10000
#define N_EDGES 640000
#define TE 256

typedef uint32_t u32;

// ---------------- device scratch ----------------
__device__ float g_hagg[N_NODES * 128];
__device__ float g_cagg4[N_NODES * 4];
__device__ float g_P[N_NODES * 128];
__device__ float g_Q[N_NODES * 128];
__device__ uint4 g_Bf2[8 * 512];         // We2 3-term
__device__ uint2 g_Bf3[8 * 512];         // Wc1 hi-only
__device__ uint4 g_Bfn1[16 * 512];       // Wn1 3-term (K=256)
__device__ uint4 g_Bfn2[8 * 512];        // Wn2 3-term
__device__ uint4 g_Bfp[8 * 512];         // We1[0:128] 3-term
__device__ uint4 g_Bfq[8 * 512];         // We1[128:256] 3-term

__device__ __forceinline__ float silu_f(float x) { return x / (1.0f + __expf(-x)); }

__device__ __forceinline__ u32 bf16x2_rn(float x0, float x1) {
    u32 r; asm("cvt.rn.bf16x2.f32 %0, %1, %2;" : "=r"(r) : "f"(x1), "f"(x0)); return r;
}
__device__ __forceinline__ u32 bf16x2_lo(float x0, float x1, u32 h) {
    float h0 = __uint_as_float(h << 16);
    float h1 = __uint_as_float(h & 0xffff0000u);
    return bf16x2_rn(x0 - h0, x1 - h1);
}
__device__ __forceinline__ u32 smem_u32(const void* p) {
    u32 a;
    asm("{ .reg .u64 t; cvta.to.shared.u64 t, %1; cvt.u32.u64 %0, t; }"
        : "=r"(a) : "l"(p));
    return a;
}
__device__ __forceinline__ void ldsm_x4(u32* r, u32 addr) {
    asm volatile("ldmatrix.sync.aligned.m8n8.x4.shared.b16 {%0,%1,%2,%3}, [%4];"
        : "=r"(r[0]), "=r"(r[1]), "=r"(r[2]), "=r"(r[3]) : "r"(addr));
}
__device__ __forceinline__ void red_v4(float* p, float4 v) {
    asm volatile("red.global.add.v4.f32 [%0], {%1,%2,%3,%4};"
        :: "l"(p), "f"(v.x), "f"(v.y), "f"(v.z), "f"(v.w) : "memory");
}
__device__ __forceinline__ void red_v2(float* p, float a, float b) {
    asm volatile("red.global.add.v2.f32 [%0], {%1,%2};"
        :: "l"(p), "f"(a), "f"(b) : "memory");
}

#define MMA_BF16(d, a0, a1, a2, a3, b0, b1)                                 \
    asm volatile(                                                           \
        "mma.sync.aligned.m16n8k16.row.col.f32.bf16.bf16.f32 "              \
        "{%0,%1,%2,%3},{%4,%5,%6,%7},{%8,%9},{%0,%1,%2,%3};"                \
        : "+f"((d)[0]), "+f"((d)[1]), "+f"((d)[2]), "+f"((d)[3])            \
        : "r"(a0), "r"(a1), "r"(a2), "r"(a3), "r"(b0), "r"(b1))

// ---------------- prep: weights -> bf16 fragments ----------------
__global__ void prep_kernel(const float* __restrict__ We1,
                            const float* __restrict__ We2,
                            const float* __restrict__ Wc1,
                            const float* __restrict__ Wn1,
                            const float* __restrict__ Wn2)
{
    int i = blockIdx.x * blockDim.x + threadIdx.x;
    const float* W; int idx, mode;
    if (i < 4096)        { W = We2; idx = i;         mode = 0; }
    else if (i < 8192)   { W = Wc1; idx = i - 4096;  mode = 1; }
    else if (i < 16384)  { W = Wn1; idx = i - 8192;  mode = 2; }
    else if (i < 20480)  { W = Wn2; idx = i - 16384; mode = 3; }
    else if (i < 24576)  { W = We1;             idx = i - 20480; mode = 4; }
    else if (i < 28672)  { W = We1 + 128 * 128; idx = i - 24576; mode = 5; }
    else return;

    int c = idx >> 9, rem = idx & 511;
    int t = rem >> 5, l = rem & 31;
    int g = l >> 2, tig = l & 3;
    int n = t * 8 + g;
    int k0 = c * 16 + 2 * tig;
    float w0 = W[(k0    ) * 128 + n];
    float w1 = W[(k0 + 1) * 128 + n];
    float w2 = W[(k0 + 8) * 128 + n];
    float w3 = W[(k0 + 9) * 128 + n];
    u32 bh01 = bf16x2_rn(w0, w1), bh23 = bf16x2_rn(w2, w3);
    u32 bl01 = bf16x2_lo(w0, w1, bh01), bl23 = bf16x2_lo(w2, w3, bh23);
    uint4 v4 = make_uint4(bh01, bh23, bl01, bl23);
    if (mode == 0)      g_Bf2[idx]  = v4;
    else if (mode == 1) g_Bf3[idx]  = make_uint2(bh01, bh23);
    else if (mode == 2) g_Bfn1[idx] = v4;
    else if (mode == 3) g_Bfn2[idx] = v4;
    else if (mode == 4) g_Bfp[idx]  = v4;
    else                g_Bfq[idx]  = v4;
}

__global__ void zero_kernel()
{
    int i = blockIdx.x * blockDim.x + threadIdx.x;
    int st = gridDim.x * blockDim.x;
    for (int k = i; k < N_NODES * 128; k += st) g_hagg[k] = 0.0f;
    for (int k = i; k < N_NODES * 4;   k += st) g_cagg4[k] = 0.0f;
}

// ---------------- bf16 mma cores ----------------
template<int KC>
__device__ __forceinline__ void mma3(
    u32 AhiA, u32 AloA, int SA,
    const uint4* __restrict__ Bf, float acc[2][4][4],
    int m0, int ntb, int lane)
{
    int arow = (m0 + (lane & 15)) * SA + ((lane >> 4) << 2);
    u32 h0 = AhiA + arow * 4, h1 = h0 + 16 * SA * 4;
    u32 l0 = AloA + arow * 4, l1 = l0 + 16 * SA * 4;
#pragma unroll
    for (int c = 0; c < KC; c++) {
        uint4 bf[4];
#pragma unroll
        for (int nt = 0; nt < 4; nt++)
            bf[nt] = __ldg(Bf + (c * 16 + ntb + nt) * 32 + lane);
        u32 ah[2][4], al[2][4];
        ldsm_x4(ah[0], h0 + c * 32);
        ldsm_x4(ah[1], h1 + c * 32);
        ldsm_x4(al[0], l0 + c * 32);
        ldsm_x4(al[1], l1 + c * 32);
#pragma unroll
        for (int nt = 0; nt < 4; nt++) {
#pragma unroll
            for (int mt = 0; mt < 2; mt++) {
                MMA_BF16(acc[mt][nt], ah[mt][0], ah[mt][1], ah[mt][2], ah[mt][3],
                         bf[nt].x, bf[nt].y);
                MMA_BF16(acc[mt][nt], al[mt][0], al[mt][1], al[mt][2], al[mt][3],
                         bf[nt].x, bf[nt].y);
                MMA_BF16(acc[mt][nt], ah[mt][0], ah[mt][1], ah[mt][2], ah[mt][3],
                         bf[nt].z, bf[nt].w);
            }
        }
    }
}

template<int KC>
__device__ __forceinline__ void mma1t(
    u32 AhiA, int SA,
    const uint2* __restrict__ Bf, float acc[2][4][4],
    int m0, int ntb, int lane)
{
    int arow = (m0 + (lane & 15)) * SA + ((lane >> 4) << 2);
    u32 h0 = AhiA + arow * 4, h1 = h0 + 16 * SA * 4;
#pragma unroll
    for (int c = 0; c < KC; c++) {
        uint2 bf[4];
#pragma unroll
        for (int nt = 0; nt < 4; nt++)
            bf[nt] = __ldg(Bf + (c * 16 + ntb + nt) * 32 + lane);
        u32 ah[2][4];
        ldsm_x4(ah[0], h0 + c * 32);
        ldsm_x4(ah[1], h1 + c * 32);
#pragma unroll
        for (int nt = 0; nt < 4; nt++) {
#pragma unroll
            for (int mt = 0; mt < 2; mt++) {
                MMA_BF16(acc[mt][nt], ah[mt][0], ah[mt][1], ah[mt][2], ah[mt][3],
                         bf[nt].x, bf[nt].y);
            }
        }
    }
}

#define ZACC(acc) do { _Pragma("unroll") for (int a_ = 0; a_ < 2; a_++) \
    _Pragma("unroll") for (int b_ = 0; b_ < 4; b_++) \
    _Pragma("unroll") for (int c_ = 0; c_ < 4; c_++) acc[a_][b_][c_] = 0.0f; } while (0)

#define SH 68

// ---------------- pre: P/Q = h @ We1 halves (bf16 mma) ----------------
#define POFF_AHI 0
#define POFF_ALO 4352
#define POFF_MISC 8704
#define PRE_SMEM_BYTES ((POFF_MISC + 128) * 4)

__global__ void __launch_bounds__(TE, 3)
pre_mma_kernel(const float* __restrict__ h, const float* __restrict__ be1)
{
    extern __shared__ u32 smu[];
    u32* Ahi = smu + POFF_AHI;
    u32* Alo = smu + POFF_ALO;
    float* s_be1 = (float*)(smu + POFF_MISC);

    const int tid  = threadIdx.x;
    const int lane = tid & 31;
    const int wid  = tid >> 5;
    const int g    = lane >> 2;
    const int tig  = lane & 3;
    const int mw   = wid >> 2;
    const int nw   = wid & 3;
    const int m0   = mw * 32;
    const int ntb  = nw * 4;
    const int n0   = blockIdx.x * 64;

    const u32 smb = smem_u32(smu);
    const u32 AhiA = smb + POFF_AHI * 4;
    const u32 AloA = smb + POFF_ALO * 4;

    if (tid < 128) s_be1[tid] = be1[tid];

    // gather h -> bf16 hi/lo
    for (int t = wid; t < 64; t += 8) {
        int n = n0 + t;
        float4 v = make_float4(0.f, 0.f, 0.f, 0.f);
        if (n < N_NODES) v = __ldg((const float4*)(h + (size_t)n * 128) + lane);
        u32 h0 = bf16x2_rn(v.x, v.y), h1 = bf16x2_rn(v.z, v.w);
        int o = t * SH + lane * 2;
        *(uint2*)&Ahi[o] = make_uint2(h0, h1);
        *(uint2*)&Alo[o] = make_uint2(bf16x2_lo(v.x, v.y, h0), bf16x2_lo(v.z, v.w, h1));
    }
    __syncthreads();

    float acc[2][4][4];

    // P = h @ We1_top + be1
    ZACC(acc);
    mma3<8>(AhiA, AloA, SH, g_Bfp, acc, m0, ntb, lane);
#pragma unroll
    for (int mt = 0; mt < 2; mt++) {
        int ra = m0 + mt * 16 + g, rb = ra + 8;
        int na = n0 + ra, nb = n0 + rb;
#pragma unroll
        for (int nt = 0; nt < 4; nt++) {
            int col = (ntb + nt) * 8 + 2 * tig;
            float b0 = s_be1[col], b1 = s_be1[col + 1];
            if (na < N_NODES)
                *(float2*)&g_P[(size_t)na * 128 + col] =
                    make_float2(acc[mt][nt][0] + b0, acc[mt][nt][1] + b1);
            if (nb < N_NODES)
                *(float2*)&g_P[(size_t)nb * 128 + col] =
                    make_float2(acc[mt][nt][2] + b0, acc[mt][nt][3] + b1);
        }
    }

    // Q = h @ We1_bot
    ZACC(acc);
    mma3<8>(AhiA, AloA, SH, g_Bfq, acc, m0, ntb, lane);
#pragma unroll
    for (int mt = 0; mt < 2; mt++) {
        int ra = m0 + mt * 16 + g, rb = ra + 8;
        int na = n0 + ra, nb = n0 + rb;
#pragma unroll
        for (int nt = 0; nt < 4; nt++) {
            int col = (ntb + nt) * 8 + 2 * tig;
            if (na < N_NODES)
                *(float2*)&g_Q[(size_t)na * 128 + col] =
                    make_float2(acc[mt][nt][0], acc[mt][nt][1]);
            if (nb < N_NODES)
                *(float2*)&g_Q[(size_t)nb * 128 + col] =
                    make_float2(acc[mt][nt][2], acc[mt][nt][3]);
        }
    }
}

// ---------------- edge kernel (round-10 config) ----------------
#define OFF_HIDH 0
#define OFF_HIDL 4352
#define OFF_EFH  8704
#define OFF_MISC 13056
#define SMEM_EDGE_U32 (OFF_MISC + 1152)
#define SMEM_EDGE_BYTES (SMEM_EDGE_U32 * 4)

__global__ void __launch_bounds__(TE, 3)
edge_kernel(const float* __restrict__ y, const int* __restrict__ ei,
            const float* __restrict__ w256,
            const float* __restrict__ be2, const float* __restrict__ bc1,
            const float* __restrict__ Wc2)
{
    extern __shared__ u32 smu[];
    u32* hidH = smu + OFF_HIDH;
    u32* hidL = smu + OFF_HIDL;
    u32* efH  = smu + OFF_EFH;
    float* s_w256 = (float*)(smu + OFF_MISC);
    float* s_be2  = s_w256 + 128;
    float* s_bc1  = s_be2 + 128;
    float* s_wc2  = s_bc1 + 128;
    float* s_rad  = s_wc2 + 128;
    float* s_diff = s_rad + 64;
    float* s_part = s_diff + 192;
    int*   s_row  = (int*)(s_part + 256);
    int*   s_col  = s_row + 64;

    const int tid  = threadIdx.x;
    const int lane = tid & 31;
    const int wid  = tid >> 5;
    const int g    = lane >> 2;
    const int tig  = lane & 3;
    const int mw   = wid >> 2;
    const int nw   = wid & 3;
    const int m0   = mw * 32;
    const int ntb  = nw * 4;
    const int e0g  = blockIdx.x * 64;

    const u32 smb   = smem_u32(smu);
    const u32 hidHa = smb + OFF_HIDH * 4;
    const u32 hidLa = smb + OFF_HIDL * 4;
    const u32 efHa  = smb + OFF_EFH * 4;

    if (tid < 64) {
        int r = ei[e0g + tid], c = ei[N_EDGES + e0g + tid];
        s_row[tid] = r; s_col[tid] = c;
        float dx = y[r*3+0]-y[c*3+0], dy = y[r*3+1]-y[c*3+1], dz = y[r*3+2]-y[c*3+2];
        s_diff[tid*3+0] = dx; s_diff[tid*3+1] = dy; s_diff[tid*3+2] = dz;
        s_rad[tid] = dx*dx + dy*dy + dz*dz;
    }
    if (tid < 128) {
        s_w256[tid] = w256[tid];
        s_be2[tid] = be2[tid]; s_bc1[tid] = bc1[tid]; s_wc2[tid] = Wc2[tid];
    }
    __syncthreads();

    // ---- fused former-GEMM1: hid = silu(P[row] + Q[col] + rad*w256) ----
#pragma unroll 2
    for (int t = wid; t < 64; t += 8) {
        int rnode = s_row[t], cnode = s_col[t];
        float4 p = __ldg((const float4*)(g_P + (size_t)rnode * 128) + lane);
        float4 q = __ldg((const float4*)(g_Q + (size_t)cnode * 128) + lane);
        float rad = s_rad[t];
        float4 w = *(const float4*)&s_w256[lane * 4];
        float v0 = silu_f(p.x + q.x + rad * w.x);
        float v1 = silu_f(p.y + q.y + rad * w.y);
        float v2 = silu_f(p.z + q.z + rad * w.z);
        float v3 = silu_f(p.w + q.w + rad * w.w);
        u32 h0 = bf16x2_rn(v0, v1), h1 = bf16x2_rn(v2, v3);
        int o = t * SH + lane * 2;
        *(uint2*)&hidH[o] = make_uint2(h0, h1);
        *(uint2*)&hidL[o] = make_uint2(bf16x2_lo(v0, v1, h0), bf16x2_lo(v2, v3, h1));
    }
    __syncthreads();

    float acc[2][4][4];

    // ---- GEMM2: hid @ We2 (3-term) ----
    ZACC(acc);
    mma3<8>(hidHa, hidLa, SH, g_Bf2, acc, m0, ntb, lane);
#pragma unroll
    for (int mt = 0; mt < 2; mt++) {
        int ra = m0 + mt * 16 + g, rb = ra + 8;
        size_t na = (size_t)s_row[ra] * 128, nb = (size_t)s_row[rb] * 128;
#pragma unroll
        for (int nt = 0; nt < 4; nt++) {
            int col = (ntb + nt) * 8 + 2 * tig;
            int uc  = (ntb + nt) * 4 + tig;
            float b0 = s_be2[col], b1 = s_be2[col + 1];
            float v0 = silu_f(acc[mt][nt][0] + b0), v1 = silu_f(acc[mt][nt][1] + b1);
            float v2 = silu_f(acc[mt][nt][2] + b0), v3 = silu_f(acc[mt][nt][3] + b1);
            efH[ra * SH + uc] = bf16x2_rn(v0, v1);
            efH[rb * SH + uc] = bf16x2_rn(v2, v3);
            red_v2(&g_hagg[na + col], v0, v1);
            red_v2(&g_hagg[nb + col], v2, v3);
        }
    }
    __syncthreads();

    // ---- GEMM3: ef @ Wc1 (1-term, coord path) ----
    ZACC(acc);
    mma1t<8>(efHa, SH, g_Bf3, acc, m0, ntb, lane);
    {
        float p[4] = {0.f, 0.f, 0.f, 0.f};
#pragma unroll
        for (int mt = 0; mt < 2; mt++) {
#pragma unroll
            for (int nt = 0; nt < 4; nt++) {
                int col = (ntb + nt) * 8 + 2 * tig;
                float b0 = s_bc1[col], b1 = s_bc1[col + 1];
                float w0 = s_wc2[col], w1 = s_wc2[col + 1];
                p[mt*2+0] += silu_f(acc[mt][nt][0] + b0) * w0
                           + silu_f(acc[mt][nt][1] + b1) * w1;
                p[mt*2+1] += silu_f(acc[mt][nt][2] + b0) * w0
                           + silu_f(acc[mt][nt][3] + b1) * w1;
            }
        }
#pragma unroll
        for (int i = 0; i < 4; i++) {
            p[i] += __shfl_xor_sync(0xffffffffu, p[i], 1);
            p[i] += __shfl_xor_sync(0xffffffffu, p[i], 2);
        }
        if (tig == 0) {
#pragma unroll
            for (int mt = 0; mt < 2; mt++) {
                s_part[nw * 64 + m0 + mt * 16 + g]     = p[mt*2+0];
                s_part[nw * 64 + m0 + mt * 16 + g + 8] = p[mt*2+1];
            }
        }
    }
    __syncthreads();

    if (tid < 64) {
        float s = s_part[tid] + s_part[64 + tid] + s_part[128 + tid] + s_part[192 + tid];
        float4 v = make_float4(s_diff[tid*3+0] * s, s_diff[tid*3+1] * s,
                               s_diff[tid*3+2] * s, 1.0f);
        red_v4(&g_cagg4[s_row[tid] * 4], v);
    }
}

// ---------------- node kernel: bf16 mma ----------------
#define SHN 132
#define NOFF_AHI 0
#define NOFF_ALO 8448
#define NOFF_HH  16896
#define NOFF_HL  21248
#define NOFF_MISC 25600
#define SMEM_NODE_BYTES ((NOFF_MISC + 256) * 4)

__global__ void __launch_bounds__(TE, 1)
node_mma_kernel(const float* __restrict__ h, const float* __restrict__ y,
                const float* __restrict__ bn1, const float* __restrict__ bn2,
                float* __restrict__ out_h, float* __restrict__ out_y)
{
    extern __shared__ u32 smu[];
    u32* AhiN = smu + NOFF_AHI;
    u32* AloN = smu + NOFF_ALO;
    u32* hidH = smu + NOFF_HH;
    u32* hidL = smu + NOFF_HL;
    float* s_bn1 = (float*)(smu + NOFF_MISC);
    float* s_bn2 = s_bn1 + 128;

    const int tid  = threadIdx.x;
    const int lane = tid & 31;
    const int wid  = tid >> 5;
    const int g    = lane >> 2;
    const int tig  = lane & 3;
    const int mw   = wid >> 2;
    const int nw   = wid & 3;
    const int m0   = mw * 32;
    const int ntb  = nw * 4;
    const int n0   = blockIdx.x * 64;

    const u32 smb = smem_u32(smu);
    const u32 AhiA = smb + NOFF_AHI * 4;
    const u32 AloA = smb + NOFF_ALO * 4;
    const u32 hHa  = smb + NOFF_HH * 4;
    const u32 hLa  = smb + NOFF_HL * 4;

    if (tid < 128) { s_bn1[tid] = bn1[tid]; s_bn2[tid] = bn2[tid]; }

    for (int t = wid; t < 128; t += 8) {
        int r = t >> 1, half = t & 1, n = n0 + r;
        float4 v = make_float4(0.f, 0.f, 0.f, 0.f);
        if (n < N_NODES) {
            const float* src = half ? (g_hagg + (size_t)n * 128) : (h + (size_t)n * 128);
            v = __ldg((const float4*)src + lane);
        }
        u32 h0 = bf16x2_rn(v.x, v.y), h1 = bf16x2_rn(v.z, v.w);
        int o = r * SHN + half * 64 + lane * 2;
        *(uint2*)&AhiN[o] = make_uint2(h0, h1);
        *(uint2*)&AloN[o] = make_uint2(bf16x2_lo(v.x, v.y, h0), bf16x2_lo(v.z, v.w, h1));
    }
    __syncthreads();

    float acc[2][4][4];

    ZACC(acc);
    mma3<16>(AhiA, AloA, SHN, g_Bfn1, acc, m0, ntb, lane);
#pragma unroll
    for (int mt = 0; mt < 2; mt++) {
        int ra = m0 + mt * 16 + g, rb = ra + 8;
#pragma unroll
        for (int nt = 0; nt < 4; nt++) {
            int col = (ntb + nt) * 8 + 2 * tig;
            int uc  = (ntb + nt) * 4 + tig;
            float b0 = s_bn1[col], b1 = s_bn1[col + 1];
            float v0 = silu_f(acc[mt][nt][0] + b0), v1 = silu_f(acc[mt][nt][1] + b1);
            float v2 = silu_f(acc[mt][nt][2] + b0), v3 = silu_f(acc[mt][nt][3] + b1);
            u32 ha = bf16x2_rn(v0, v1), hb = bf16x2_rn(v2, v3);
            hidH[ra * SH + uc] = ha; hidL[ra * SH + uc] = bf16x2_lo(v0, v1, ha);
            hidH[rb * SH + uc] = hb; hidL[rb * SH + uc] = bf16x2_lo(v2, v3, hb);
        }
    }
    __syncthreads();

    ZACC(acc);
    mma3<8>(hHa, hLa, SH, g_Bfn2, acc, m0, ntb, lane);
#pragma unroll
    for (int mt = 0; mt < 2; mt++) {
        int ra = m0 + mt * 16 + g, rb = ra + 8;
        int na = n0 + ra, nb = n0 + rb;
#pragma unroll
        for (int nt = 0; nt < 4; nt++) {
            int col = (ntb + nt) * 8 + 2 * tig;
            float b0 = s_bn2[col], b1 = s_bn2[col + 1];
            if (na < N_NODES) {
                float2 hh = __ldg((const float2*)(h + (size_t)na * 128 + col));
                *(float2*)&out_h[(size_t)na * 128 + col] =
                    make_float2(acc[mt][nt][0] + b0 + hh.x, acc[mt][nt][1] + b1 + hh.y);
            }
            if (nb < N_NODES) {
                float2 hh = __ldg((const float2*)(h + (size_t)nb * 128 + col));
                *(float2*)&out_h[(size_t)nb * 128 + col] =
                    make_float2(acc[mt][nt][2] + b0 + hh.x, acc[mt][nt][3] + b1 + hh.y);
            }
        }
    }

    if (tid < 64) {
        int n = n0 + tid;
        if (n < N_NODES) {
            float c = g_cagg4[n * 4 + 3]; c = (c < 1.0f) ? 1.0f : c;
            out_y[n*3+0] = y[n*3+0] + g_cagg4[n*4+0] / c;
            out_y[n*3+1] = y[n*3+1] + g_cagg4[n*4+1] / c;
            out_y[n*3+2] = y[n*3+2] + g_cagg4[n*4+2] / c;
        }
    }
}

extern "C" void kernel_launch(void* const* d_in, const int* in_sizes, int n_in,
                              void* d_out, int out_size)
{
    const float* h   = (const float*)d_in[0];
    const float* y   = (const float*)d_in[1];
    const int*   ei  = (const int*)d_in[2];
    const float* We1 = (const float*)d_in[3];
    const float* be1 = (const float*)d_in[4];
    const float* We2 = (const float*)d_in[5];
    const float* be2 = (const float*)d_in[6];
    const float* Wc1 = (const float*)d_in[7];
    const float* bc1 = (const float*)d_in[8];
    const float* Wc2 = (const float*)d_in[9];
    const float* Wn1 = (const float*)d_in[10];
    const float* bn1 = (const float*)d_in[11];
    const float* Wn2 = (const float*)d_in[12];
    const float* bn2 = (const float*)d_in[13];

    float* out_h = (float*)d_out;
    float* out_y = out_h + (size_t)N_NODES * 128;

    cudaFuncSetAttribute(edge_kernel, cudaFuncAttributeMaxDynamicSharedMemorySize,
                         SMEM_EDGE_BYTES);
    cudaFuncSetAttribute(node_mma_kernel, cudaFuncAttributeMaxDynamicSharedMemorySize,
                         SMEM_NODE_BYTES);
    cudaFuncSetAttribute(pre_mma_kernel, cudaFuncAttributeMaxDynamicSharedMemorySize,
                         PRE_SMEM_BYTES);

    zero_kernel<<<512, TE>>>();
    prep_kernel<<<112, 256>>>(We1, We2, Wc1, Wn1, Wn2);
    pre_mma_kernel<<<(N_NODES + 63) / 64, TE, PRE_SMEM_BYTES>>>(h, be1);

    edge_kernel<<<N_EDGES / 64, TE, SMEM_EDGE_BYTES>>>(
        y, ei, We1 + 256 * 128, be2, bc1, Wc2);

    node_mma_kernel<<<(N_NODES + 63) / 64, TE, SMEM_NODE_BYTES>>>(
        h, y, bn1, bn2, out_h, out_y);
}

// round 13
// speedup vs baseline: 1.3414x; 1.0227x over previous
#include <cuda_runtime.h>
#include <cstdint>

#define N_NODES 10000
#define N_EDGES 640000
#define TE 256

typedef uint32_t u32;

// ---------------- device scratch ----------------
__device__ float g_hagg[N_NODES * 128];
__device__ float g_cagg4[N_NODES * 4];
__device__ float g_P[N_NODES * 128];
__device__ float g_Q[N_NODES * 128];
__device__ uint4 g_Bf2[8 * 512];         // We2 3-term
__device__ uint2 g_Bf3[8 * 512];         // Wc1 hi-only
__device__ uint4 g_Bfn1[16 * 512];       // Wn1 3-term (K=256)
__device__ uint4 g_Bfn2[8 * 512];        // Wn2 3-term
__device__ uint4 g_Bfp[8 * 512];         // We1[0:128] 3-term
__device__ uint4 g_Bfq[8 * 512];         // We1[128:256] 3-term

__device__ __forceinline__ float silu_f(float x) { return x / (1.0f + __expf(-x)); }

__device__ __forceinline__ u32 bf16x2_rn(float x0, float x1) {
    u32 r; asm("cvt.rn.bf16x2.f32 %0, %1, %2;" : "=r"(r) : "f"(x1), "f"(x0)); return r;
}
__device__ __forceinline__ u32 bf16x2_lo(float x0, float x1, u32 h) {
    float h0 = __uint_as_float(h << 16);
    float h1 = __uint_as_float(h & 0xffff0000u);
    return bf16x2_rn(x0 - h0, x1 - h1);
}
__device__ __forceinline__ u32 smem_u32(const void* p) {
    u32 a;
    asm("{ .reg .u64 t; cvta.to.shared.u64 t, %1; cvt.u32.u64 %0, t; }"
        : "=r"(a) : "l"(p));
    return a;
}
__device__ __forceinline__ void ldsm_x4(u32* r, u32 addr) {
    asm volatile("ldmatrix.sync.aligned.m8n8.x4.shared.b16 {%0,%1,%2,%3}, [%4];"
        : "=r"(r[0]), "=r"(r[1]), "=r"(r[2]), "=r"(r[3]) : "r"(addr));
}
__device__ __forceinline__ void red_v4(float* p, float4 v) {
    asm volatile("red.global.add.v4.f32 [%0], {%1,%2,%3,%4};"
        :: "l"(p), "f"(v.x), "f"(v.y), "f"(v.z), "f"(v.w) : "memory");
}
__device__ __forceinline__ void red_v2(float* p, float a, float b) {
    asm volatile("red.global.add.v2.f32 [%0], {%1,%2};"
        :: "l"(p), "f"(a), "f"(b) : "memory");
}

#define MMA_BF16(d, a0, a1, a2, a3, b0, b1)                                 \
    asm volatile(                                                           \
        "mma.sync.aligned.m16n8k16.row.col.f32.bf16.bf16.f32 "              \
        "{%0,%1,%2,%3},{%4,%5,%6,%7},{%8,%9},{%0,%1,%2,%3};"                \
        : "+f"((d)[0]), "+f"((d)[1]), "+f"((d)[2]), "+f"((d)[3])            \
        : "r"(a0), "r"(a1), "r"(a2), "r"(a3), "r"(b0), "r"(b1))

// ---------------- zero + weight-fragment prep (merged) ----------------
// blocks [0,112): weight fragments; blocks [112,624): zero hagg/cagg
__global__ void zp_kernel(const float* __restrict__ We1,
                          const float* __restrict__ We2,
                          const float* __restrict__ Wc1,
                          const float* __restrict__ Wn1,
                          const float* __restrict__ Wn2)
{
    if (blockIdx.x >= 112) {
        int i = (blockIdx.x - 112) * blockDim.x + threadIdx.x;
        int st = 512 * blockDim.x;
        for (int k = i; k < N_NODES * 128; k += st) g_hagg[k] = 0.0f;
        for (int k = i; k < N_NODES * 4;   k += st) g_cagg4[k] = 0.0f;
        return;
    }
    int i = blockIdx.x * blockDim.x + threadIdx.x;
    const float* W; int idx, mode;
    if (i < 4096)        { W = We2; idx = i;         mode = 0; }
    else if (i < 8192)   { W = Wc1; idx = i - 4096;  mode = 1; }
    else if (i < 16384)  { W = Wn1; idx = i - 8192;  mode = 2; }
    else if (i < 20480)  { W = Wn2; idx = i - 16384; mode = 3; }
    else if (i < 24576)  { W = We1;             idx = i - 20480; mode = 4; }
    else                 { W = We1 + 128 * 128; idx = i - 24576; mode = 5; }

    int c = idx >> 9, rem = idx & 511;
    int t = rem >> 5, l = rem & 31;
    int g = l >> 2, tig = l & 3;
    int n = t * 8 + g;
    int k0 = c * 16 + 2 * tig;
    float w0 = W[(k0    ) * 128 + n];
    float w1 = W[(k0 + 1) * 128 + n];
    float w2 = W[(k0 + 8) * 128 + n];
    float w3 = W[(k0 + 9) * 128 + n];
    u32 bh01 = bf16x2_rn(w0, w1), bh23 = bf16x2_rn(w2, w3);
    u32 bl01 = bf16x2_lo(w0, w1, bh01), bl23 = bf16x2_lo(w2, w3, bh23);
    uint4 v4 = make_uint4(bh01, bh23, bl01, bl23);
    if (mode == 0)      g_Bf2[idx]  = v4;
    else if (mode == 1) g_Bf3[idx]  = make_uint2(bh01, bh23);
    else if (mode == 2) g_Bfn1[idx] = v4;
    else if (mode == 3) g_Bfn2[idx] = v4;
    else if (mode == 4) g_Bfp[idx]  = v4;
    else                g_Bfq[idx]  = v4;
}

// ---------------- bf16 mma cores ----------------
template<int KC>
__device__ __forceinline__ void mma3(
    u32 AhiA, u32 AloA, int SA,
    const uint4* __restrict__ Bf, float acc[2][4][4],
    int m0, int ntb, int lane)
{
    int arow = (m0 + (lane & 15)) * SA + ((lane >> 4) << 2);
    u32 h0 = AhiA + arow * 4, h1 = h0 + 16 * SA * 4;
    u32 l0 = AloA + arow * 4, l1 = l0 + 16 * SA * 4;
#pragma unroll
    for (int c = 0; c < KC; c++) {
        uint4 bf[4];
#pragma unroll
        for (int nt = 0; nt < 4; nt++)
            bf[nt] = __ldg(Bf + (c * 16 + ntb + nt) * 32 + lane);
        u32 ah[2][4], al[2][4];
        ldsm_x4(ah[0], h0 + c * 32);
        ldsm_x4(ah[1], h1 + c * 32);
        ldsm_x4(al[0], l0 + c * 32);
        ldsm_x4(al[1], l1 + c * 32);
#pragma unroll
        for (int nt = 0; nt < 4; nt++) {
#pragma unroll
            for (int mt = 0; mt < 2; mt++) {
                MMA_BF16(acc[mt][nt], ah[mt][0], ah[mt][1], ah[mt][2], ah[mt][3],
                         bf[nt].x, bf[nt].y);
                MMA_BF16(acc[mt][nt], al[mt][0], al[mt][1], al[mt][2], al[mt][3],
                         bf[nt].x, bf[nt].y);
                MMA_BF16(acc[mt][nt], ah[mt][0], ah[mt][1], ah[mt][2], ah[mt][3],
                         bf[nt].z, bf[nt].w);
            }
        }
    }
}

template<int KC>
__device__ __forceinline__ void mma1t(
    u32 AhiA, int SA,
    const uint2* __restrict__ Bf, float acc[2][4][4],
    int m0, int ntb, int lane)
{
    int arow = (m0 + (lane & 15)) * SA + ((lane >> 4) << 2);
    u32 h0 = AhiA + arow * 4, h1 = h0 + 16 * SA * 4;
#pragma unroll
    for (int c = 0; c < KC; c++) {
        uint2 bf[4];
#pragma unroll
        for (int nt = 0; nt < 4; nt++)
            bf[nt] = __ldg(Bf + (c * 16 + ntb + nt) * 32 + lane);
        u32 ah[2][4];
        ldsm_x4(ah[0], h0 + c * 32);
        ldsm_x4(ah[1], h1 + c * 32);
#pragma unroll
        for (int nt = 0; nt < 4; nt++) {
#pragma unroll
            for (int mt = 0; mt < 2; mt++) {
                MMA_BF16(acc[mt][nt], ah[mt][0], ah[mt][1], ah[mt][2], ah[mt][3],
                         bf[nt].x, bf[nt].y);
            }
        }
    }
}

#define ZACC(acc) do { _Pragma("unroll") for (int a_ = 0; a_ < 2; a_++) \
    _Pragma("unroll") for (int b_ = 0; b_ < 4; b_++) \
    _Pragma("unroll") for (int c_ = 0; c_ < 4; c_++) acc[a_][b_][c_] = 0.0f; } while (0)

#define SH 68

// ---------------- pre: P/Q = h @ We1 halves (bf16 mma) ----------------
#define POFF_AHI 0
#define POFF_ALO 4352
#define POFF_MISC 8704
#define PRE_SMEM_BYTES ((POFF_MISC + 128) * 4)

__global__ void __launch_bounds__(TE, 3)
pre_mma_kernel(const float* __restrict__ h, const float* __restrict__ be1)
{
    extern __shared__ u32 smu[];
    u32* Ahi = smu + POFF_AHI;
    u32* Alo = smu + POFF_ALO;
    float* s_be1 = (float*)(smu + POFF_MISC);

    const int tid  = threadIdx.x;
    const int lane = tid & 31;
    const int wid  = tid >> 5;
    const int g    = lane >> 2;
    const int tig  = lane & 3;
    const int mw   = wid >> 2;
    const int nw   = wid & 3;
    const int m0   = mw * 32;
    const int ntb  = nw * 4;
    const int n0   = blockIdx.x * 64;

    const u32 smb = smem_u32(smu);
    const u32 AhiA = smb + POFF_AHI * 4;
    const u32 AloA = smb + POFF_ALO * 4;

    if (tid < 128) s_be1[tid] = be1[tid];

    for (int t = wid; t < 64; t += 8) {
        int n = n0 + t;
        float4 v = make_float4(0.f, 0.f, 0.f, 0.f);
        if (n < N_NODES) v = __ldg((const float4*)(h + (size_t)n * 128) + lane);
        u32 h0 = bf16x2_rn(v.x, v.y), h1 = bf16x2_rn(v.z, v.w);
        int o = t * SH + lane * 2;
        *(uint2*)&Ahi[o] = make_uint2(h0, h1);
        *(uint2*)&Alo[o] = make_uint2(bf16x2_lo(v.x, v.y, h0), bf16x2_lo(v.z, v.w, h1));
    }
    __syncthreads();

    float acc[2][4][4];

    ZACC(acc);
    mma3<8>(AhiA, AloA, SH, g_Bfp, acc, m0, ntb, lane);
#pragma unroll
    for (int mt = 0; mt < 2; mt++) {
        int ra = m0 + mt * 16 + g, rb = ra + 8;
        int na = n0 + ra, nb = n0 + rb;
#pragma unroll
        for (int nt = 0; nt < 4; nt++) {
            int col = (ntb + nt) * 8 + 2 * tig;
            float b0 = s_be1[col], b1 = s_be1[col + 1];
            if (na < N_NODES)
                *(float2*)&g_P[(size_t)na * 128 + col] =
                    make_float2(acc[mt][nt][0] + b0, acc[mt][nt][1] + b1);
            if (nb < N_NODES)
                *(float2*)&g_P[(size_t)nb * 128 + col] =
                    make_float2(acc[mt][nt][2] + b0, acc[mt][nt][3] + b1);
        }
    }

    ZACC(acc);
    mma3<8>(AhiA, AloA, SH, g_Bfq, acc, m0, ntb, lane);
#pragma unroll
    for (int mt = 0; mt < 2; mt++) {
        int ra = m0 + mt * 16 + g, rb = ra + 8;
        int na = n0 + ra, nb = n0 + rb;
#pragma unroll
        for (int nt = 0; nt < 4; nt++) {
            int col = (ntb + nt) * 8 + 2 * tig;
            if (na < N_NODES)
                *(float2*)&g_Q[(size_t)na * 128 + col] =
                    make_float2(acc[mt][nt][0], acc[mt][nt][1]);
            if (nb < N_NODES)
                *(float2*)&g_Q[(size_t)nb * 128 + col] =
                    make_float2(acc[mt][nt][2], acc[mt][nt][3]);
        }
    }
}

// ---------------- edge kernel (round-12 config, unchanged) ----------------
#define OFF_HIDH 0
#define OFF_HIDL 4352
#define OFF_EFH  8704
#define OFF_MISC 13056
#define SMEM_EDGE_U32 (OFF_MISC + 1152)
#define SMEM_EDGE_BYTES (SMEM_EDGE_U32 * 4)

__global__ void __launch_bounds__(TE, 3)
edge_kernel(const float* __restrict__ y, const int* __restrict__ ei,
            const float* __restrict__ w256,
            const float* __restrict__ be2, const float* __restrict__ bc1,
            const float* __restrict__ Wc2)
{
    extern __shared__ u32 smu[];
    u32* hidH = smu + OFF_HIDH;
    u32* hidL = smu + OFF_HIDL;
    u32* efH  = smu + OFF_EFH;
    float* s_w256 = (float*)(smu + OFF_MISC);
    float* s_be2  = s_w256 + 128;
    float* s_bc1  = s_be2 + 128;
    float* s_wc2  = s_bc1 + 128;
    float* s_rad  = s_wc2 + 128;
    float* s_diff = s_rad + 64;
    float* s_part = s_diff + 192;
    int*   s_row  = (int*)(s_part + 256);
    int*   s_col  = s_row + 64;

    const int tid  = threadIdx.x;
    const int lane = tid & 31;
    const int wid  = tid >> 5;
    const int g    = lane >> 2;
    const int tig  = lane & 3;
    const int mw   = wid >> 2;
    const int nw   = wid & 3;
    const int m0   = mw * 32;
    const int ntb  = nw * 4;
    const int e0g  = blockIdx.x * 64;

    const u32 smb   = smem_u32(smu);
    const u32 hidHa = smb + OFF_HIDH * 4;
    const u32 hidLa = smb + OFF_HIDL * 4;
    const u32 efHa  = smb + OFF_EFH * 4;

    if (tid < 64) {
        int r = ei[e0g + tid], c = ei[N_EDGES + e0g + tid];
        s_row[tid] = r; s_col[tid] = c;
        float dx = y[r*3+0]-y[c*3+0], dy = y[r*3+1]-y[c*3+1], dz = y[r*3+2]-y[c*3+2];
        s_diff[tid*3+0] = dx; s_diff[tid*3+1] = dy; s_diff[tid*3+2] = dz;
        s_rad[tid] = dx*dx + dy*dy + dz*dz;
    }
    if (tid < 128) {
        s_w256[tid] = w256[tid];
        s_be2[tid] = be2[tid]; s_bc1[tid] = bc1[tid]; s_wc2[tid] = Wc2[tid];
    }
    __syncthreads();

#pragma unroll 2
    for (int t = wid; t < 64; t += 8) {
        int rnode = s_row[t], cnode = s_col[t];
        float4 p = __ldg((const float4*)(g_P + (size_t)rnode * 128) + lane);
        float4 q = __ldg((const float4*)(g_Q + (size_t)cnode * 128) + lane);
        float rad = s_rad[t];
        float4 w = *(const float4*)&s_w256[lane * 4];
        float v0 = silu_f(p.x + q.x + rad * w.x);
        float v1 = silu_f(p.y + q.y + rad * w.y);
        float v2 = silu_f(p.z + q.z + rad * w.z);
        float v3 = silu_f(p.w + q.w + rad * w.w);
        u32 h0 = bf16x2_rn(v0, v1), h1 = bf16x2_rn(v2, v3);
        int o = t * SH + lane * 2;
        *(uint2*)&hidH[o] = make_uint2(h0, h1);
        *(uint2*)&hidL[o] = make_uint2(bf16x2_lo(v0, v1, h0), bf16x2_lo(v2, v3, h1));
    }
    __syncthreads();

    float acc[2][4][4];

    ZACC(acc);
    mma3<8>(hidHa, hidLa, SH, g_Bf2, acc, m0, ntb, lane);
#pragma unroll
    for (int mt = 0; mt < 2; mt++) {
        int ra = m0 + mt * 16 + g, rb = ra + 8;
        size_t na = (size_t)s_row[ra] * 128, nb = (size_t)s_row[rb] * 128;
#pragma unroll
        for (int nt = 0; nt < 4; nt++) {
            int col = (ntb + nt) * 8 + 2 * tig;
            int uc  = (ntb + nt) * 4 + tig;
            float b0 = s_be2[col], b1 = s_be2[col + 1];
            float v0 = silu_f(acc[mt][nt][0] + b0), v1 = silu_f(acc[mt][nt][1] + b1);
            float v2 = silu_f(acc[mt][nt][2] + b0), v3 = silu_f(acc[mt][nt][3] + b1);
            efH[ra * SH + uc] = bf16x2_rn(v0, v1);
            efH[rb * SH + uc] = bf16x2_rn(v2, v3);
            red_v2(&g_hagg[na + col], v0, v1);
            red_v2(&g_hagg[nb + col], v2, v3);
        }
    }
    __syncthreads();

    ZACC(acc);
    mma1t<8>(efHa, SH, g_Bf3, acc, m0, ntb, lane);
    {
        float p[4] = {0.f, 0.f, 0.f, 0.f};
#pragma unroll
        for (int mt = 0; mt < 2; mt++) {
#pragma unroll
            for (int nt = 0; nt < 4; nt++) {
                int col = (ntb + nt) * 8 + 2 * tig;
                float b0 = s_bc1[col], b1 = s_bc1[col + 1];
                float w0 = s_wc2[col], w1 = s_wc2[col + 1];
                p[mt*2+0] += silu_f(acc[mt][nt][0] + b0) * w0
                           + silu_f(acc[mt][nt][1] + b1) * w1;
                p[mt*2+1] += silu_f(acc[mt][nt][2] + b0) * w0
                           + silu_f(acc[mt][nt][3] + b1) * w1;
            }
        }
#pragma unroll
        for (int i = 0; i < 4; i++) {
            p[i] += __shfl_xor_sync(0xffffffffu, p[i], 1);
            p[i] += __shfl_xor_sync(0xffffffffu, p[i], 2);
        }
        if (tig == 0) {
#pragma unroll
            for (int mt = 0; mt < 2; mt++) {
                s_part[nw * 64 + m0 + mt * 16 + g]     = p[mt*2+0];
                s_part[nw * 64 + m0 + mt * 16 + g + 8] = p[mt*2+1];
            }
        }
    }
    __syncthreads();

    if (tid < 64) {
        float s = s_part[tid] + s_part[64 + tid] + s_part[128 + tid] + s_part[192 + tid];
        float4 v = make_float4(s_diff[tid*3+0] * s, s_diff[tid*3+1] * s,
                               s_diff[tid*3+2] * s, 1.0f);
        red_v4(&g_cagg4[s_row[tid] * 4], v);
    }
}

// ---------------- node kernel: bf16 mma, overlaid SMEM (3 CTAs) ----------------
#define SHN 132
#define NOFF_AHI 0
#define NOFF_ALO 8448
#define NOFF_HH  0          // overlays AhiN after GEMM1 (sync-guarded)
#define NOFF_HL  4352
#define NOFF_MISC 16896
#define SMEM_NODE_BYTES ((NOFF_MISC + 256) * 4)

__global__ void __launch_bounds__(TE, 3)
node_mma_kernel(const float* __restrict__ h, const float* __restrict__ y,
                const float* __restrict__ bn1, const float* __restrict__ bn2,
                float* __restrict__ out_h, float* __restrict__ out_y)
{
    extern __shared__ u32 smu[];
    u32* AhiN = smu + NOFF_AHI;
    u32* AloN = smu + NOFF_ALO;
    u32* hidH = smu + NOFF_HH;
    u32* hidL = smu + NOFF_HL;
    float* s_bn1 = (float*)(smu + NOFF_MISC);
    float* s_bn2 = s_bn1 + 128;

    const int tid  = threadIdx.x;
    const int lane = tid & 31;
    const int wid  = tid >> 5;
    const int g    = lane >> 2;
    const int tig  = lane & 3;
    const int mw   = wid >> 2;
    const int nw   = wid & 3;
    const int m0   = mw * 32;
    const int ntb  = nw * 4;
    const int n0   = blockIdx.x * 64;

    const u32 smb = smem_u32(smu);
    const u32 AhiA = smb + NOFF_AHI * 4;
    const u32 AloA = smb + NOFF_ALO * 4;
    const u32 hHa  = smb + NOFF_HH * 4;
    const u32 hLa  = smb + NOFF_HL * 4;

    if (tid < 128) { s_bn1[tid] = bn1[tid]; s_bn2[tid] = bn2[tid]; }

    for (int t = wid; t < 128; t += 8) {
        int r = t >> 1, half = t & 1, n = n0 + r;
        float4 v = make_float4(0.f, 0.f, 0.f, 0.f);
        if (n < N_NODES) {
            const float* src = half ? (g_hagg + (size_t)n * 128) : (h + (size_t)n * 128);
            v = __ldg((const float4*)src + lane);
        }
        u32 h0 = bf16x2_rn(v.x, v.y), h1 = bf16x2_rn(v.z, v.w);
        int o = r * SHN + half * 64 + lane * 2;
        *(uint2*)&AhiN[o] = make_uint2(h0, h1);
        *(uint2*)&AloN[o] = make_uint2(bf16x2_lo(v.x, v.y, h0), bf16x2_lo(v.z, v.w, h1));
    }
    __syncthreads();

    float acc[2][4][4];

    ZACC(acc);
    mma3<16>(AhiA, AloA, SHN, g_Bfn1, acc, m0, ntb, lane);
    __syncthreads();   // all A reads done before hid overlays A region
#pragma unroll
    for (int mt = 0; mt < 2; mt++) {
        int ra = m0 + mt * 16 + g, rb = ra + 8;
#pragma unroll
        for (int nt = 0; nt < 4; nt++) {
            int col = (ntb + nt) * 8 + 2 * tig;
            int uc  = (ntb + nt) * 4 + tig;
            float b0 = s_bn1[col], b1 = s_bn1[col + 1];
            float v0 = silu_f(acc[mt][nt][0] + b0), v1 = silu_f(acc[mt][nt][1] + b1);
            float v2 = silu_f(acc[mt][nt][2] + b0), v3 = silu_f(acc[mt][nt][3] + b1);
            u32 ha = bf16x2_rn(v0, v1), hb = bf16x2_rn(v2, v3);
            hidH[ra * SH + uc] = ha; hidL[ra * SH + uc] = bf16x2_lo(v0, v1, ha);
            hidH[rb * SH + uc] = hb; hidL[rb * SH + uc] = bf16x2_lo(v2, v3, hb);
        }
    }
    __syncthreads();

    ZACC(acc);
    mma3<8>(hHa, hLa, SH, g_Bfn2, acc, m0, ntb, lane);
#pragma unroll
    for (int mt = 0; mt < 2; mt++) {
        int ra = m0 + mt * 16 + g, rb = ra + 8;
        int na = n0 + ra, nb = n0 + rb;
#pragma unroll
        for (int nt = 0; nt < 4; nt++) {
            int col = (ntb + nt) * 8 + 2 * tig;
            float b0 = s_bn2[col], b1 = s_bn2[col + 1];
            if (na < N_NODES) {
                float2 hh = __ldg((const float2*)(h + (size_t)na * 128 + col));
                *(float2*)&out_h[(size_t)na * 128 + col] =
                    make_float2(acc[mt][nt][0] + b0 + hh.x, acc[mt][nt][1] + b1 + hh.y);
            }
            if (nb < N_NODES) {
                float2 hh = __ldg((const float2*)(h + (size_t)nb * 128 + col));
                *(float2*)&out_h[(size_t)nb * 128 + col] =
                    make_float2(acc[mt][nt][2] + b0 + hh.x, acc[mt][nt][3] + b1 + hh.y);
            }
        }
    }

    if (tid < 64) {
        int n = n0 + tid;
        if (n < N_NODES) {
            float c = g_cagg4[n * 4 + 3]; c = (c < 1.0f) ? 1.0f : c;
            out_y[n*3+0] = y[n*3+0] + g_cagg4[n*4+0] / c;
            out_y[n*3+1] = y[n*3+1] + g_cagg4[n*4+1] / c;
            out_y[n*3+2] = y[n*3+2] + g_cagg4[n*4+2] / c;
        }
    }
}

extern "C" void kernel_launch(void* const* d_in, const int* in_sizes, int n_in,
                              void* d_out, int out_size)
{
    const float* h   = (const float*)d_in[0];
    const float* y   = (const float*)d_in[1];
    const int*   ei  = (const int*)d_in[2];
    const float* We1 = (const float*)d_in[3];
    const float* be1 = (const float*)d_in[4];
    const float* We2 = (const float*)d_in[5];
    const float* be2 = (const float*)d_in[6];
    const float* Wc1 = (const float*)d_in[7];
    const float* bc1 = (const float*)d_in[8];
    const float* Wc2 = (const float*)d_in[9];
    const float* Wn1 = (const float*)d_in[10];
    const float* bn1 = (const float*)d_in[11];
    const float* Wn2 = (const float*)d_in[12];
    const float* bn2 = (const float*)d_in[13];

    float* out_h = (float*)d_out;
    float* out_y = out_h + (size_t)N_NODES * 128;

    cudaFuncSetAttribute(edge_kernel, cudaFuncAttributeMaxDynamicSharedMemorySize,
                         SMEM_EDGE_BYTES);
    cudaFuncSetAttribute(node_mma_kernel, cudaFuncAttributeMaxDynamicSharedMemorySize,
                         SMEM_NODE_BYTES);
    cudaFuncSetAttribute(pre_mma_kernel, cudaFuncAttributeMaxDynamicSharedMemorySize,
                         PRE_SMEM_BYTES);

    zp_kernel<<<624, TE>>>(We1, We2, Wc1, Wn1, Wn2);
    pre_mma_kernel<<<(N_NODES + 63) / 64, TE, PRE_SMEM_BYTES>>>(h, be1);

    edge_kernel<<<N_EDGES / 64, TE, SMEM_EDGE_BYTES>>>(
        y, ei, We1 + 256 * 128, be2, bc1, Wc2);

    node_mma_kernel<<<(N_NODES + 63) / 64, TE, SMEM_NODE_BYTES>>>(
        h, y, bn1, bn2, out_h, out_y);
}

// round 14
// speedup vs baseline: 1.3551x; 1.0102x over previous
#include <cuda_runtime.h>
#include <cstdint>

#define N_NODES 10000
#define N_EDGES 640000
#define TE 256

typedef uint32_t u32;

// ---------------- device scratch ----------------
__device__ float g_hagg[N_NODES * 128];
__device__ float g_cagg4[N_NODES * 4];
__device__ float g_P[N_NODES * 128];
__device__ float g_Q[N_NODES * 128];
__device__ uint4 g_Bf2[8 * 512];         // We2 3-term (column-permuted)
__device__ uint2 g_Bf3[8 * 512];         // Wc1 hi-only
__device__ uint4 g_Bfn1[16 * 512];       // Wn1 3-term (K=256)
__device__ uint4 g_Bfn2[8 * 512];        // Wn2 3-term
__device__ uint4 g_Bfp[8 * 512];         // We1[0:128] 3-term
__device__ uint4 g_Bfq[8 * 512];         // We1[128:256] 3-term

__device__ __forceinline__ float silu_f(float x) { return x / (1.0f + __expf(-x)); }

__device__ __forceinline__ u32 bf16x2_rn(float x0, float x1) {
    u32 r; asm("cvt.rn.bf16x2.f32 %0, %1, %2;" : "=r"(r) : "f"(x1), "f"(x0)); return r;
}
__device__ __forceinline__ u32 bf16x2_lo(float x0, float x1, u32 h) {
    float h0 = __uint_as_float(h << 16);
    float h1 = __uint_as_float(h & 0xffff0000u);
    return bf16x2_rn(x0 - h0, x1 - h1);
}
__device__ __forceinline__ u32 smem_u32(const void* p) {
    u32 a;
    asm("{ .reg .u64 t; cvta.to.shared.u64 t, %1; cvt.u32.u64 %0, t; }"
        : "=r"(a) : "l"(p));
    return a;
}
__device__ __forceinline__ void ldsm_x4(u32* r, u32 addr) {
    asm volatile("ldmatrix.sync.aligned.m8n8.x4.shared.b16 {%0,%1,%2,%3}, [%4];"
        : "=r"(r[0]), "=r"(r[1]), "=r"(r[2]), "=r"(r[3]) : "r"(addr));
}
__device__ __forceinline__ void red_v4(float* p, float4 v) {
    asm volatile("red.global.add.v4.f32 [%0], {%1,%2,%3,%4};"
        :: "l"(p), "f"(v.x), "f"(v.y), "f"(v.z), "f"(v.w) : "memory");
}

#define MMA_BF16(d, a0, a1, a2, a3, b0, b1)                                 \
    asm volatile(                                                           \
        "mma.sync.aligned.m16n8k16.row.col.f32.bf16.bf16.f32 "              \
        "{%0,%1,%2,%3},{%4,%5,%6,%7},{%8,%9},{%0,%1,%2,%3};"                \
        : "+f"((d)[0]), "+f"((d)[1]), "+f"((d)[2]), "+f"((d)[3])            \
        : "r"(a0), "r"(a1), "r"(a2), "r"(a3), "r"(b0), "r"(b1))

// ---------------- zero + weight-fragment prep (merged) ----------------
__global__ void zp_kernel(const float* __restrict__ We1,
                          const float* __restrict__ We2,
                          const float* __restrict__ Wc1,
                          const float* __restrict__ Wn1,
                          const float* __restrict__ Wn2)
{
    if (blockIdx.x >= 112) {
        int i = (blockIdx.x - 112) * blockDim.x + threadIdx.x;
        int st = 512 * blockDim.x;
        for (int k = i; k < N_NODES * 128; k += st) g_hagg[k] = 0.0f;
        for (int k = i; k < N_NODES * 4;   k += st) g_cagg4[k] = 0.0f;
        return;
    }
    int i = blockIdx.x * blockDim.x + threadIdx.x;
    const float* W; int idx, mode;
    if (i < 4096)        { W = We2; idx = i;         mode = 0; }
    else if (i < 8192)   { W = Wc1; idx = i - 4096;  mode = 1; }
    else if (i < 16384)  { W = Wn1; idx = i - 8192;  mode = 2; }
    else if (i < 20480)  { W = Wn2; idx = i - 16384; mode = 3; }
    else if (i < 24576)  { W = We1;             idx = i - 20480; mode = 4; }
    else                 { W = We1 + 128 * 128; idx = i - 24576; mode = 5; }

    int c = idx >> 9, rem = idx & 511;
    int t = rem >> 5, l = rem & 31;
    int g = l >> 2, tig = l & 3;
    int n;
    if (mode == 0) {
        // column permutation: acc pos (t, g) -> actual col
        n = 16 * (t >> 1) + 4 * (g >> 1) + 2 * (t & 1) + (g & 1);
    } else {
        n = t * 8 + g;
    }
    int k0 = c * 16 + 2 * tig;
    float w0 = W[(k0    ) * 128 + n];
    float w1 = W[(k0 + 1) * 128 + n];
    float w2 = W[(k0 + 8) * 128 + n];
    float w3 = W[(k0 + 9) * 128 + n];
    u32 bh01 = bf16x2_rn(w0, w1), bh23 = bf16x2_rn(w2, w3);
    u32 bl01 = bf16x2_lo(w0, w1, bh01), bl23 = bf16x2_lo(w2, w3, bh23);
    uint4 v4 = make_uint4(bh01, bh23, bl01, bl23);
    if (mode == 0)      g_Bf2[idx]  = v4;
    else if (mode == 1) g_Bf3[idx]  = make_uint2(bh01, bh23);
    else if (mode == 2) g_Bfn1[idx] = v4;
    else if (mode == 3) g_Bfn2[idx] = v4;
    else if (mode == 4) g_Bfp[idx]  = v4;
    else                g_Bfq[idx]  = v4;
}

// ---------------- bf16 mma cores ----------------
template<int KC>
__device__ __forceinline__ void mma3(
    u32 AhiA, u32 AloA, int SA,
    const uint4* __restrict__ Bf, float acc[2][4][4],
    int m0, int ntb, int lane)
{
    int arow = (m0 + (lane & 15)) * SA + ((lane >> 4) << 2);
    u32 h0 = AhiA + arow * 4, h1 = h0 + 16 * SA * 4;
    u32 l0 = AloA + arow * 4, l1 = l0 + 16 * SA * 4;
#pragma unroll
    for (int c = 0; c < KC; c++) {
        uint4 bf[4];
#pragma unroll
        for (int nt = 0; nt < 4; nt++)
            bf[nt] = __ldg(Bf + (c * 16 + ntb + nt) * 32 + lane);
        u32 ah[2][4], al[2][4];
        ldsm_x4(ah[0], h0 + c * 32);
        ldsm_x4(ah[1], h1 + c * 32);
        ldsm_x4(al[0], l0 + c * 32);
        ldsm_x4(al[1], l1 + c * 32);
#pragma unroll
        for (int nt = 0; nt < 4; nt++) {
#pragma unroll
            for (int mt = 0; mt < 2; mt++) {
                MMA_BF16(acc[mt][nt], ah[mt][0], ah[mt][1], ah[mt][2], ah[mt][3],
                         bf[nt].x, bf[nt].y);
                MMA_BF16(acc[mt][nt], al[mt][0], al[mt][1], al[mt][2], al[mt][3],
                         bf[nt].x, bf[nt].y);
                MMA_BF16(acc[mt][nt], ah[mt][0], ah[mt][1], ah[mt][2], ah[mt][3],
                         bf[nt].z, bf[nt].w);
            }
        }
    }
}

template<int KC>
__device__ __forceinline__ void mma1t(
    u32 AhiA, int SA,
    const uint2* __restrict__ Bf, float acc[2][4][4],
    int m0, int ntb, int lane)
{
    int arow = (m0 + (lane & 15)) * SA + ((lane >> 4) << 2);
    u32 h0 = AhiA + arow * 4, h1 = h0 + 16 * SA * 4;
#pragma unroll
    for (int c = 0; c < KC; c++) {
        uint2 bf[4];
#pragma unroll
        for (int nt = 0; nt < 4; nt++)
            bf[nt] = __ldg(Bf + (c * 16 + ntb + nt) * 32 + lane);
        u32 ah[2][4];
        ldsm_x4(ah[0], h0 + c * 32);
        ldsm_x4(ah[1], h1 + c * 32);
#pragma unroll
        for (int nt = 0; nt < 4; nt++) {
#pragma unroll
            for (int mt = 0; mt < 2; mt++) {
                MMA_BF16(acc[mt][nt], ah[mt][0], ah[mt][1], ah[mt][2], ah[mt][3],
                         bf[nt].x, bf[nt].y);
            }
        }
    }
}

#define ZACC(acc) do { _Pragma("unroll") for (int a_ = 0; a_ < 2; a_++) \
    _Pragma("unroll") for (int b_ = 0; b_ < 4; b_++) \
    _Pragma("unroll") for (int c_ = 0; c_ < 4; c_++) acc[a_][b_][c_] = 0.0f; } while (0)

#define SH 68

// ---------------- pre: P/Q = h @ We1 halves (bf16 mma) ----------------
#define POFF_AHI 0
#define POFF_ALO 4352
#define POFF_MISC 8704
#define PRE_SMEM_BYTES ((POFF_MISC + 128) * 4)

__global__ void __launch_bounds__(TE, 3)
pre_mma_kernel(const float* __restrict__ h, const float* __restrict__ be1)
{
    extern __shared__ u32 smu[];
    u32* Ahi = smu + POFF_AHI;
    u32* Alo = smu + POFF_ALO;
    float* s_be1 = (float*)(smu + POFF_MISC);

    const int tid  = threadIdx.x;
    const int lane = tid & 31;
    const int wid  = tid >> 5;
    const int g    = lane >> 2;
    const int tig  = lane & 3;
    const int mw   = wid >> 2;
    const int nw   = wid & 3;
    const int m0   = mw * 32;
    const int ntb  = nw * 4;
    const int n0   = blockIdx.x * 64;

    const u32 smb = smem_u32(smu);
    const u32 AhiA = smb + POFF_AHI * 4;
    const u32 AloA = smb + POFF_ALO * 4;

    if (tid < 128) s_be1[tid] = be1[tid];

    for (int t = wid; t < 64; t += 8) {
        int n = n0 + t;
        float4 v = make_float4(0.f, 0.f, 0.f, 0.f);
        if (n < N_NODES) v = __ldg((const float4*)(h + (size_t)n * 128) + lane);
        u32 h0 = bf16x2_rn(v.x, v.y), h1 = bf16x2_rn(v.z, v.w);
        int o = t * SH + lane * 2;
        *(uint2*)&Ahi[o] = make_uint2(h0, h1);
        *(uint2*)&Alo[o] = make_uint2(bf16x2_lo(v.x, v.y, h0), bf16x2_lo(v.z, v.w, h1));
    }
    __syncthreads();

    float acc[2][4][4];

    ZACC(acc);
    mma3<8>(AhiA, AloA, SH, g_Bfp, acc, m0, ntb, lane);
#pragma unroll
    for (int mt = 0; mt < 2; mt++) {
        int ra = m0 + mt * 16 + g, rb = ra + 8;
        int na = n0 + ra, nb = n0 + rb;
#pragma unroll
        for (int nt = 0; nt < 4; nt++) {
            int col = (ntb + nt) * 8 + 2 * tig;
            float b0 = s_be1[col], b1 = s_be1[col + 1];
            if (na < N_NODES)
                *(float2*)&g_P[(size_t)na * 128 + col] =
                    make_float2(acc[mt][nt][0] + b0, acc[mt][nt][1] + b1);
            if (nb < N_NODES)
                *(float2*)&g_P[(size_t)nb * 128 + col] =
                    make_float2(acc[mt][nt][2] + b0, acc[mt][nt][3] + b1);
        }
    }

    ZACC(acc);
    mma3<8>(AhiA, AloA, SH, g_Bfq, acc, m0, ntb, lane);
#pragma unroll
    for (int mt = 0; mt < 2; mt++) {
        int ra = m0 + mt * 16 + g, rb = ra + 8;
        int na = n0 + ra, nb = n0 + rb;
#pragma unroll
        for (int nt = 0; nt < 4; nt++) {
            int col = (ntb + nt) * 8 + 2 * tig;
            if (na < N_NODES)
                *(float2*)&g_Q[(size_t)na * 128 + col] =
                    make_float2(acc[mt][nt][0], acc[mt][nt][1]);
            if (nb < N_NODES)
                *(float2*)&g_Q[(size_t)nb * 128 + col] =
                    make_float2(acc[mt][nt][2], acc[mt][nt][3]);
        }
    }
}

// ---------------- edge kernel ----------------
#define OFF_HIDH 0
#define OFF_HIDL 4352
#define OFF_EFH  8704
#define OFF_MISC 13056
#define SMEM_EDGE_U32 (OFF_MISC + 1152)
#define SMEM_EDGE_BYTES (SMEM_EDGE_U32 * 4)

__global__ void __launch_bounds__(TE, 3)
edge_kernel(const float* __restrict__ y, const int* __restrict__ ei,
            const float* __restrict__ w256,
            const float* __restrict__ be2, const float* __restrict__ bc1,
            const float* __restrict__ Wc2)
{
    extern __shared__ u32 smu[];
    u32* hidH = smu + OFF_HIDH;
    u32* hidL = smu + OFF_HIDL;
    u32* efH  = smu + OFF_EFH;
    float* s_w256 = (float*)(smu + OFF_MISC);
    float* s_be2  = s_w256 + 128;
    float* s_bc1  = s_be2 + 128;
    float* s_wc2  = s_bc1 + 128;
    float* s_rad  = s_wc2 + 128;
    float* s_diff = s_rad + 64;
    float* s_part = s_diff + 192;
    int*   s_row  = (int*)(s_part + 256);
    int*   s_col  = s_row + 64;

    const int tid  = threadIdx.x;
    const int lane = tid & 31;
    const int wid  = tid >> 5;
    const int g    = lane >> 2;
    const int tig  = lane & 3;
    const int mw   = wid >> 2;
    const int nw   = wid & 3;
    const int m0   = mw * 32;
    const int ntb  = nw * 4;
    const int e0g  = blockIdx.x * 64;

    const u32 smb   = smem_u32(smu);
    const u32 hidHa = smb + OFF_HIDH * 4;
    const u32 hidLa = smb + OFF_HIDL * 4;
    const u32 efHa  = smb + OFF_EFH * 4;

    if (tid < 64) {
        int r = ei[e0g + tid], c = ei[N_EDGES + e0g + tid];
        s_row[tid] = r; s_col[tid] = c;
        float dx = y[r*3+0]-y[c*3+0], dy = y[r*3+1]-y[c*3+1], dz = y[r*3+2]-y[c*3+2];
        s_diff[tid*3+0] = dx; s_diff[tid*3+1] = dy; s_diff[tid*3+2] = dz;
        s_rad[tid] = dx*dx + dy*dy + dz*dz;
    }
    if (tid < 128) {
        s_w256[tid] = w256[tid];
        s_be2[tid] = be2[tid]; s_bc1[tid] = bc1[tid]; s_wc2[tid] = Wc2[tid];
    }
    __syncthreads();

    // ---- fused former-GEMM1: hid = silu(P[row] + Q[col] + rad*w256) ----
#pragma unroll 2
    for (int t = wid; t < 64; t += 8) {
        int rnode = s_row[t], cnode = s_col[t];
        float4 p = __ldg((const float4*)(g_P + (size_t)rnode * 128) + lane);
        float4 q = __ldg((const float4*)(g_Q + (size_t)cnode * 128) + lane);
        float rad = s_rad[t];
        float4 w = *(const float4*)&s_w256[lane * 4];
        float v0 = silu_f(p.x + q.x + rad * w.x);
        float v1 = silu_f(p.y + q.y + rad * w.y);
        float v2 = silu_f(p.z + q.z + rad * w.z);
        float v3 = silu_f(p.w + q.w + rad * w.w);
        u32 h0 = bf16x2_rn(v0, v1), h1 = bf16x2_rn(v2, v3);
        int o = t * SH + lane * 2;
        *(uint2*)&hidH[o] = make_uint2(h0, h1);
        *(uint2*)&hidL[o] = make_uint2(bf16x2_lo(v0, v1, h0), bf16x2_lo(v2, v3, h1));
    }
    __syncthreads();

    float acc[2][4][4];

    // ---- GEMM2: hid @ We2 (3-term, permuted columns) ----
    ZACC(acc);
    mma3<8>(hidHa, hidLa, SH, g_Bf2, acc, m0, ntb, lane);
    // epilogue: acc (nt-pair, tig) -> 4 consecutive actual columns
#pragma unroll
    for (int mt = 0; mt < 2; mt++) {
        int ra = m0 + mt * 16 + g, rb = ra + 8;
        size_t na = (size_t)s_row[ra] * 128, nb = (size_t)s_row[rb] * 128;
#pragma unroll
        for (int j = 0; j < 2; j++) {
            int q  = (ntb >> 1) + j;          // 16-col group index
            int cb = 16 * q + 4 * tig;        // actual col base (4 consecutive)
            float b0 = s_be2[cb], b1 = s_be2[cb+1], b2 = s_be2[cb+2], b3 = s_be2[cb+3];
            float* A0 = acc[mt][2*j];
            float* A1 = acc[mt][2*j + 1];
            float r0 = silu_f(A0[0] + b0), r1 = silu_f(A0[1] + b1);
            float r2 = silu_f(A1[0] + b2), r3 = silu_f(A1[1] + b3);
            float s0 = silu_f(A0[2] + b0), s1 = silu_f(A0[3] + b1);
            float s2 = silu_f(A1[2] + b2), s3 = silu_f(A1[3] + b3);
            int u = 8 * q + 2 * tig;          // natural-order bf16x2 index
            *(uint2*)&efH[ra * SH + u] = make_uint2(bf16x2_rn(r0, r1), bf16x2_rn(r2, r3));
            *(uint2*)&efH[rb * SH + u] = make_uint2(bf16x2_rn(s0, s1), bf16x2_rn(s2, s3));
            red_v4(&g_hagg[na + cb], make_float4(r0, r1, r2, r3));
            red_v4(&g_hagg[nb + cb], make_float4(s0, s1, s2, s3));
        }
    }
    __syncthreads();

    // ---- GEMM3: ef @ Wc1 (1-term, natural order) ----
    ZACC(acc);
    mma1t<8>(efHa, SH, g_Bf3, acc, m0, ntb, lane);
    {
        float p[4] = {0.f, 0.f, 0.f, 0.f};
#pragma unroll
        for (int mt = 0; mt < 2; mt++) {
#pragma unroll
            for (int nt = 0; nt < 4; nt++) {
                int col = (ntb + nt) * 8 + 2 * tig;
                float b0 = s_bc1[col], b1 = s_bc1[col + 1];
                float w0 = s_wc2[col], w1 = s_wc2[col + 1];
                p[mt*2+0] += silu_f(acc[mt][nt][0] + b0) * w0
                           + silu_f(acc[mt][nt][1] + b1) * w1;
                p[mt*2+1] += silu_f(acc[mt][nt][2] + b0) * w0
                           + silu_f(acc[mt][nt][3] + b1) * w1;
            }
        }
#pragma unroll
        for (int i = 0; i < 4; i++) {
            p[i] += __shfl_xor_sync(0xffffffffu, p[i], 1);
            p[i] += __shfl_xor_sync(0xffffffffu, p[i], 2);
        }
        if (tig == 0) {
#pragma unroll
            for (int mt = 0; mt < 2; mt++) {
                s_part[nw * 64 + m0 + mt * 16 + g]     = p[mt*2+0];
                s_part[nw * 64 + m0 + mt * 16 + g + 8] = p[mt*2+1];
            }
        }
    }
    __syncthreads();

    if (tid < 64) {
        float s = s_part[tid] + s_part[64 + tid] + s_part[128 + tid] + s_part[192 + tid];
        float4 v = make_float4(s_diff[tid*3+0] * s, s_diff[tid*3+1] * s,
                               s_diff[tid*3+2] * s, 1.0f);
        red_v4(&g_cagg4[s_row[tid] * 4], v);
    }
}

// ---------------- node kernel: bf16 mma, overlaid SMEM (3 CTAs) ----------------
#define SHN 132
#define NOFF_AHI 0
#define NOFF_ALO 8448
#define NOFF_HH  0
#define NOFF_HL  4352
#define NOFF_MISC 16896
#define SMEM_NODE_BYTES ((NOFF_MISC + 256) * 4)

__global__ void __launch_bounds__(TE, 3)
node_mma_kernel(const float* __restrict__ h, const float* __restrict__ y,
                const float* __restrict__ bn1, const float* __restrict__ bn2,
                float* __restrict__ out_h, float* __restrict__ out_y)
{
    extern __shared__ u32 smu[];
    u32* AhiN = smu + NOFF_AHI;
    u32* AloN = smu + NOFF_ALO;
    u32* hidH = smu + NOFF_HH;
    u32* hidL = smu + NOFF_HL;
    float* s_bn1 = (float*)(smu + NOFF_MISC);
    float* s_bn2 = s_bn1 + 128;

    const int tid  = threadIdx.x;
    const int lane = tid & 31;
    const int wid  = tid >> 5;
    const int g    = lane >> 2;
    const int tig  = lane & 3;
    const int mw   = wid >> 2;
    const int nw   = wid & 3;
    const int m0   = mw * 32;
    const int ntb  = nw * 4;
    const int n0   = blockIdx.x * 64;

    const u32 smb = smem_u32(smu);
    const u32 AhiA = smb + NOFF_AHI * 4;
    const u32 AloA = smb + NOFF_ALO * 4;
    const u32 hHa  = smb + NOFF_HH * 4;
    const u32 hLa  = smb + NOFF_HL * 4;

    if (tid < 128) { s_bn1[tid] = bn1[tid]; s_bn2[tid] = bn2[tid]; }

    for (int t = wid; t < 128; t += 8) {
        int r = t >> 1, half = t & 1, n = n0 + r;
        float4 v = make_float4(0.f, 0.f, 0.f, 0.f);
        if (n < N_NODES) {
            const float* src = half ? (g_hagg + (size_t)n * 128) : (h + (size_t)n * 128);
            v = __ldg((const float4*)src + lane);
        }
        u32 h0 = bf16x2_rn(v.x, v.y), h1 = bf16x2_rn(v.z, v.w);
        int o = r * SHN + half * 64 + lane * 2;
        *(uint2*)&AhiN[o] = make_uint2(h0, h1);
        *(uint2*)&AloN[o] = make_uint2(bf16x2_lo(v.x, v.y, h0), bf16x2_lo(v.z, v.w, h1));
    }
    __syncthreads();

    float acc[2][4][4];

    ZACC(acc);
    mma3<16>(AhiA, AloA, SHN, g_Bfn1, acc, m0, ntb, lane);
    __syncthreads();
#pragma unroll
    for (int mt = 0; mt < 2; mt++) {
        int ra = m0 + mt * 16 + g, rb = ra + 8;
#pragma unroll
        for (int nt = 0; nt < 4; nt++) {
            int col = (ntb + nt) * 8 + 2 * tig;
            int uc  = (ntb + nt) * 4 + tig;
            float b0 = s_bn1[col], b1 = s_bn1[col + 1];
            float v0 = silu_f(acc[mt][nt][0] + b0), v1 = silu_f(acc[mt][nt][1] + b1);
            float v2 = silu_f(acc[mt][nt][2] + b0), v3 = silu_f(acc[mt][nt][3] + b1);
            u32 ha = bf16x2_rn(v0, v1), hb = bf16x2_rn(v2, v3);
            hidH[ra * SH + uc] = ha; hidL[ra * SH + uc] = bf16x2_lo(v0, v1, ha);
            hidH[rb * SH + uc] = hb; hidL[rb * SH + uc] = bf16x2_lo(v2, v3, hb);
        }
    }
    __syncthreads();

    ZACC(acc);
    mma3<8>(hHa, hLa, SH, g_Bfn2, acc, m0, ntb, lane);
#pragma unroll
    for (int mt = 0; mt < 2; mt++) {
        int ra = m0 + mt * 16 + g, rb = ra + 8;
        int na = n0 + ra, nb = n0 + rb;
#pragma unroll
        for (int nt = 0; nt < 4; nt++) {
            int col = (ntb + nt) * 8 + 2 * tig;
            float b0 = s_bn2[col], b1 = s_bn2[col + 1];
            if (na < N_NODES) {
                float2 hh = __ldg((const float2*)(h + (size_t)na * 128 + col));
                *(float2*)&out_h[(size_t)na * 128 + col] =
                    make_float2(acc[mt][nt][0] + b0 + hh.x, acc[mt][nt][1] + b1 + hh.y);
            }
            if (nb < N_NODES) {
                float2 hh = __ldg((const float2*)(h + (size_t)nb * 128 + col));
                *(float2*)&out_h[(size_t)nb * 128 + col] =
                    make_float2(acc[mt][nt][2] + b0 + hh.x, acc[mt][nt][3] + b1 + hh.y);
            }
        }
    }

    if (tid < 64) {
        int n = n0 + tid;
        if (n < N_NODES) {
            float c = g_cagg4[n * 4 + 3]; c = (c < 1.0f) ? 1.0f : c;
            out_y[n*3+0] = y[n*3+0] + g_cagg4[n*4+0] / c;
            out_y[n*3+1] = y[n*3+1] + g_cagg4[n*4+1] / c;
            out_y[n*3+2] = y[n*3+2] + g_cagg4[n*4+2] / c;
        }
    }
}

extern "C" void kernel_launch(void* const* d_in, const int* in_sizes, int n_in,
                              void* d_out, int out_size)
{
    const float* h   = (const float*)d_in[0];
    const float* y   = (const float*)d_in[1];
    const int*   ei  = (const int*)d_in[2];
    const float* We1 = (const float*)d_in[3];
    const float* be1 = (const float*)d_in[4];
    const float* We2 = (const float*)d_in[5];
    const float* be2 = (const float*)d_in[6];
    const float* Wc1 = (const float*)d_in[7];
    const float* bc1 = (const float*)d_in[8];
    const float* Wc2 = (const float*)d_in[9];
    const float* Wn1 = (const float*)d_in[10];
    const float* bn1 = (const float*)d_in[11];
    const float* Wn2 = (const float*)d_in[12];
    const float* bn2 = (const float*)d_in[13];

    float* out_h = (float*)d_out;
    float* out_y = out_h + (size_t)N_NODES * 128;

    cudaFuncSetAttribute(edge_kernel, cudaFuncAttributeMaxDynamicSharedMemorySize,
                         SMEM_EDGE_BYTES);
    cudaFuncSetAttribute(node_mma_kernel, cudaFuncAttributeMaxDynamicSharedMemorySize,
                         SMEM_NODE_BYTES);
    cudaFuncSetAttribute(pre_mma_kernel, cudaFuncAttributeMaxDynamicSharedMemorySize,
                         PRE_SMEM_BYTES);

    zp_kernel<<<624, TE>>>(We1, We2, Wc1, Wn1, Wn2);
    pre_mma_kernel<<<(N_NODES + 63) / 64, TE, PRE_SMEM_BYTES>>>(h, be1);

    edge_kernel<<<N_EDGES / 64, TE, SMEM_EDGE_BYTES>>>(
        y, ei, We1 + 256 * 128, be2, bc1, Wc2);

    node_mma_kernel<<<(N_NODES + 63) / 64, TE, SMEM_NODE_BYTES>>>(
        h, y, bn1, bn2, out_h, out_y);
}

// round 15
// speedup vs baseline: 1.3905x; 1.0261x over previous
#include <cuda_runtime.h>
#include <cstdint>

#define N_NODES 10000
#define N_EDGES 640000
#define TE 256

typedef uint32_t u32;

// ---------------- device scratch ----------------
__device__ float g_hagg[N_NODES * 128];
__device__ float g_cagg4[N_NODES * 4];
__device__ float g_P[N_NODES * 128];
__device__ float g_Q[N_NODES * 128];
__device__ uint4 g_Bf2[8 * 512];         // We2 3-term (column-permuted)
__device__ uint2 g_Bf3[8 * 512];         // Wc1 hi-only
__device__ uint4 g_Bfn1[16 * 512];       // Wn1 3-term (K=256)
__device__ uint4 g_Bfn2[8 * 512];        // Wn2 3-term
__device__ uint4 g_Bfp[8 * 512];         // We1[0:128] 3-term
__device__ uint4 g_Bfq[8 * 512];         // We1[128:256] 3-term

__device__ __forceinline__ float silu_f(float x) { return x / (1.0f + __expf(-x)); }

__device__ __forceinline__ u32 bf16x2_rn(float x0, float x1) {
    u32 r; asm("cvt.rn.bf16x2.f32 %0, %1, %2;" : "=r"(r) : "f"(x1), "f"(x0)); return r;
}
__device__ __forceinline__ u32 bf16x2_lo(float x0, float x1, u32 h) {
    float h0 = __uint_as_float(h << 16);
    float h1 = __uint_as_float(h & 0xffff0000u);
    return bf16x2_rn(x0 - h0, x1 - h1);
}
__device__ __forceinline__ u32 smem_u32(const void* p) {
    u32 a;
    asm("{ .reg .u64 t; cvta.to.shared.u64 t, %1; cvt.u32.u64 %0, t; }"
        : "=r"(a) : "l"(p));
    return a;
}
__device__ __forceinline__ void ldsm_x4(u32* r, u32 addr) {
    asm volatile("ldmatrix.sync.aligned.m8n8.x4.shared.b16 {%0,%1,%2,%3}, [%4];"
        : "=r"(r[0]), "=r"(r[1]), "=r"(r[2]), "=r"(r[3]) : "r"(addr));
}
__device__ __forceinline__ void red_v4(float* p, float4 v) {
    asm volatile("red.global.add.v4.f32 [%0], {%1,%2,%3,%4};"
        :: "l"(p), "f"(v.x), "f"(v.y), "f"(v.z), "f"(v.w) : "memory");
}

#define MMA_BF16(d, a0, a1, a2, a3, b0, b1)                                 \
    asm volatile(                                                           \
        "mma.sync.aligned.m16n8k16.row.col.f32.bf16.bf16.f32 "              \
        "{%0,%1,%2,%3},{%4,%5,%6,%7},{%8,%9},{%0,%1,%2,%3};"                \
        : "+f"((d)[0]), "+f"((d)[1]), "+f"((d)[2]), "+f"((d)[3])            \
        : "r"(a0), "r"(a1), "r"(a2), "r"(a3), "r"(b0), "r"(b1))

// ---------------- zero + weight-fragment prep (merged) ----------------
__global__ void zp_kernel(const float* __restrict__ We1,
                          const float* __restrict__ We2,
                          const float* __restrict__ Wc1,
                          const float* __restrict__ Wn1,
                          const float* __restrict__ Wn2)
{
    if (blockIdx.x >= 112) {
        int i = (blockIdx.x - 112) * blockDim.x + threadIdx.x;
        int st = 512 * blockDim.x;
        for (int k = i; k < N_NODES * 128; k += st) g_hagg[k] = 0.0f;
        for (int k = i; k < N_NODES * 4;   k += st) g_cagg4[k] = 0.0f;
        return;
    }
    int i = blockIdx.x * blockDim.x + threadIdx.x;
    const float* W; int idx, mode;
    if (i < 4096)        { W = We2; idx = i;         mode = 0; }
    else if (i < 8192)   { W = Wc1; idx = i - 4096;  mode = 1; }
    else if (i < 16384)  { W = Wn1; idx = i - 8192;  mode = 2; }
    else if (i < 20480)  { W = Wn2; idx = i - 16384; mode = 3; }
    else if (i < 24576)  { W = We1;             idx = i - 20480; mode = 4; }
    else                 { W = We1 + 128 * 128; idx = i - 24576; mode = 5; }

    int c = idx >> 9, rem = idx & 511;
    int t = rem >> 5, l = rem & 31;
    int g = l >> 2, tig = l & 3;
    int n;
    if (mode == 0) {
        n = 16 * (t >> 1) + 4 * (g >> 1) + 2 * (t & 1) + (g & 1);
    } else {
        n = t * 8 + g;
    }
    int k0 = c * 16 + 2 * tig;
    float w0 = W[(k0    ) * 128 + n];
    float w1 = W[(k0 + 1) * 128 + n];
    float w2 = W[(k0 + 8) * 128 + n];
    float w3 = W[(k0 + 9) * 128 + n];
    u32 bh01 = bf16x2_rn(w0, w1), bh23 = bf16x2_rn(w2, w3);
    u32 bl01 = bf16x2_lo(w0, w1, bh01), bl23 = bf16x2_lo(w2, w3, bh23);
    uint4 v4 = make_uint4(bh01, bh23, bl01, bl23);
    if (mode == 0)      g_Bf2[idx]  = v4;
    else if (mode == 1) g_Bf3[idx]  = make_uint2(bh01, bh23);
    else if (mode == 2) g_Bfn1[idx] = v4;
    else if (mode == 3) g_Bfn2[idx] = v4;
    else if (mode == 4) g_Bfp[idx]  = v4;
    else                g_Bfq[idx]  = v4;
}

// ---------------- bf16 mma cores (templated on ntile count) ----------------
template<int KC, int NT>
__device__ __forceinline__ void mma3(
    u32 AhiA, u32 AloA, int SA,
    const uint4* __restrict__ Bf, float acc[2][NT][4],
    int m0, int ntb, int lane)
{
    int arow = (m0 + (lane & 15)) * SA + ((lane >> 4) << 2);
    u32 h0 = AhiA + arow * 4, h1 = h0 + 16 * SA * 4;
    u32 l0 = AloA + arow * 4, l1 = l0 + 16 * SA * 4;
#pragma unroll
    for (int c = 0; c < KC; c++) {
        uint4 bf[NT];
#pragma unroll
        for (int nt = 0; nt < NT; nt++)
            bf[nt] = __ldg(Bf + (c * 16 + ntb + nt) * 32 + lane);
        u32 ah[2][4], al[2][4];
        ldsm_x4(ah[0], h0 + c * 32);
        ldsm_x4(ah[1], h1 + c * 32);
        ldsm_x4(al[0], l0 + c * 32);
        ldsm_x4(al[1], l1 + c * 32);
#pragma unroll
        for (int nt = 0; nt < NT; nt++) {
#pragma unroll
            for (int mt = 0; mt < 2; mt++) {
                MMA_BF16(acc[mt][nt], ah[mt][0], ah[mt][1], ah[mt][2], ah[mt][3],
                         bf[nt].x, bf[nt].y);
                MMA_BF16(acc[mt][nt], al[mt][0], al[mt][1], al[mt][2], al[mt][3],
                         bf[nt].x, bf[nt].y);
                MMA_BF16(acc[mt][nt], ah[mt][0], ah[mt][1], ah[mt][2], ah[mt][3],
                         bf[nt].z, bf[nt].w);
            }
        }
    }
}

template<int KC>
__device__ __forceinline__ void mma1t(
    u32 AhiA, int SA,
    const uint2* __restrict__ Bf, float acc[2][4][4],
    int m0, int ntb, int lane)
{
    int arow = (m0 + (lane & 15)) * SA + ((lane >> 4) << 2);
    u32 h0 = AhiA + arow * 4, h1 = h0 + 16 * SA * 4;
#pragma unroll
    for (int c = 0; c < KC; c++) {
        uint2 bf[4];
#pragma unroll
        for (int nt = 0; nt < 4; nt++)
            bf[nt] = __ldg(Bf + (c * 16 + ntb + nt) * 32 + lane);
        u32 ah[2][4];
        ldsm_x4(ah[0], h0 + c * 32);
        ldsm_x4(ah[1], h1 + c * 32);
#pragma unroll
        for (int nt = 0; nt < 4; nt++) {
#pragma unroll
            for (int mt = 0; mt < 2; mt++) {
                MMA_BF16(acc[mt][nt], ah[mt][0], ah[mt][1], ah[mt][2], ah[mt][3],
                         bf[nt].x, bf[nt].y);
            }
        }
    }
}

#define ZACC4(acc) do { _Pragma("unroll") for (int a_ = 0; a_ < 2; a_++) \
    _Pragma("unroll") for (int b_ = 0; b_ < 4; b_++) \
    _Pragma("unroll") for (int c_ = 0; c_ < 4; c_++) acc[a_][b_][c_] = 0.0f; } while (0)
#define ZACC2(acc) do { _Pragma("unroll") for (int a_ = 0; a_ < 2; a_++) \
    _Pragma("unroll") for (int b_ = 0; b_ < 2; b_++) \
    _Pragma("unroll") for (int c_ = 0; c_ < 4; c_++) acc[a_][b_][c_] = 0.0f; } while (0)

#define SH 68
#define SHN 132

// ---------------- pre: P/Q = h @ We1 halves, 32 nodes/block ----------------
#define POFF_ALO 4224
#define POFF_MISC 8448
#define PRE_SMEM_BYTES ((POFF_MISC + 128) * 4)

__global__ void __launch_bounds__(TE, 3)
pre_mma_kernel(const float* __restrict__ h, const float* __restrict__ be1)
{
    extern __shared__ u32 smu[];
    u32* Ahi = smu;
    u32* Alo = smu + POFF_ALO;
    float* s_be1 = (float*)(smu + POFF_MISC);

    const int tid  = threadIdx.x;
    const int lane = tid & 31;
    const int wid  = tid >> 5;
    const int g    = lane >> 2;
    const int tig  = lane & 3;
    const int ntb  = wid * 2;
    const int n0   = blockIdx.x * 32;

    const u32 smb = smem_u32(smu);
    const u32 AhiA = smb;
    const u32 AloA = smb + POFF_ALO * 4;

    if (tid < 128) s_be1[tid] = be1[tid];

    // gather h (32 rows x 128) -> bf16 hi/lo, stride SHN
    for (int t = wid; t < 64; t += 8) {
        int r = t >> 1, half = t & 1, n = n0 + r;
        float4 v = make_float4(0.f, 0.f, 0.f, 0.f);
        if (n < N_NODES) v = __ldg((const float4*)(h + (size_t)n * 128) + (half * 16 + lane / 2));
        // simpler: each (r,half) warp-iter loads 64 floats (half row)
        (void)v;
        // fall through below
        break;
    }
    // straightforward gather: warp handles 4 full rows
    for (int r = wid * 4; r < wid * 4 + 4; r++) {
        int n = n0 + r;
        float4 v = make_float4(0.f, 0.f, 0.f, 0.f);
        if (n < N_NODES) v = __ldg((const float4*)(h + (size_t)n * 128) + lane);
        u32 h0 = bf16x2_rn(v.x, v.y), h1 = bf16x2_rn(v.z, v.w);
        int o = r * SH + lane * 2;   // K=128 -> 64 u32 per row, stride SH
        *(uint2*)&Ahi[o] = make_uint2(h0, h1);
        *(uint2*)&Alo[o] = make_uint2(bf16x2_lo(v.x, v.y, h0), bf16x2_lo(v.z, v.w, h1));
    }
    __syncthreads();

    float acc[2][2][4];

    ZACC2(acc);
    mma3<8, 2>(AhiA, AloA, SH, g_Bfp, acc, 0, ntb, lane);
#pragma unroll
    for (int mt = 0; mt < 2; mt++) {
        int ra = mt * 16 + g, rb = ra + 8;
        int na = n0 + ra, nb = n0 + rb;
#pragma unroll
        for (int nt = 0; nt < 2; nt++) {
            int col = (ntb + nt) * 8 + 2 * tig;
            float b0 = s_be1[col], b1 = s_be1[col + 1];
            if (na < N_NODES)
                *(float2*)&g_P[(size_t)na * 128 + col] =
                    make_float2(acc[mt][nt][0] + b0, acc[mt][nt][1] + b1);
            if (nb < N_NODES)
                *(float2*)&g_P[(size_t)nb * 128 + col] =
                    make_float2(acc[mt][nt][2] + b0, acc[mt][nt][3] + b1);
        }
    }

    ZACC2(acc);
    mma3<8, 2>(AhiA, AloA, SH, g_Bfq, acc, 0, ntb, lane);
#pragma unroll
    for (int mt = 0; mt < 2; mt++) {
        int ra = mt * 16 + g, rb = ra + 8;
        int na = n0 + ra, nb = n0 + rb;
#pragma unroll
        for (int nt = 0; nt < 2; nt++) {
            int col = (ntb + nt) * 8 + 2 * tig;
            if (na < N_NODES)
                *(float2*)&g_Q[(size_t)na * 128 + col] =
                    make_float2(acc[mt][nt][0], acc[mt][nt][1]);
            if (nb < N_NODES)
                *(float2*)&g_Q[(size_t)nb * 128 + col] =
                    make_float2(acc[mt][nt][2], acc[mt][nt][3]);
        }
    }
}

// ---------------- edge kernel (round-14 config, unchanged) ----------------
#define OFF_HIDH 0
#define OFF_HIDL 4352
#define OFF_EFH  8704
#define OFF_MISC 13056
#define SMEM_EDGE_U32 (OFF_MISC + 1152)
#define SMEM_EDGE_BYTES (SMEM_EDGE_U32 * 4)

__global__ void __launch_bounds__(TE, 3)
edge_kernel(const float* __restrict__ y, const int* __restrict__ ei,
            const float* __restrict__ w256,
            const float* __restrict__ be2, const float* __restrict__ bc1,
            const float* __restrict__ Wc2)
{
    extern __shared__ u32 smu[];
    u32* hidH = smu + OFF_HIDH;
    u32* hidL = smu + OFF_HIDL;
    u32* efH  = smu + OFF_EFH;
    float* s_w256 = (float*)(smu + OFF_MISC);
    float* s_be2  = s_w256 + 128;
    float* s_bc1  = s_be2 + 128;
    float* s_wc2  = s_bc1 + 128;
    float* s_rad  = s_wc2 + 128;
    float* s_diff = s_rad + 64;
    float* s_part = s_diff + 192;
    int*   s_row  = (int*)(s_part + 256);
    int*   s_col  = s_row + 64;

    const int tid  = threadIdx.x;
    const int lane = tid & 31;
    const int wid  = tid >> 5;
    const int g    = lane >> 2;
    const int tig  = lane & 3;
    const int mw   = wid >> 2;
    const int nw   = wid & 3;
    const int m0   = mw * 32;
    const int ntb  = nw * 4;
    const int e0g  = blockIdx.x * 64;

    const u32 smb   = smem_u32(smu);
    const u32 hidHa = smb + OFF_HIDH * 4;
    const u32 hidLa = smb + OFF_HIDL * 4;
    const u32 efHa  = smb + OFF_EFH * 4;

    if (tid < 64) {
        int r = ei[e0g + tid], c = ei[N_EDGES + e0g + tid];
        s_row[tid] = r; s_col[tid] = c;
        float dx = y[r*3+0]-y[c*3+0], dy = y[r*3+1]-y[c*3+1], dz = y[r*3+2]-y[c*3+2];
        s_diff[tid*3+0] = dx; s_diff[tid*3+1] = dy; s_diff[tid*3+2] = dz;
        s_rad[tid] = dx*dx + dy*dy + dz*dz;
    }
    if (tid < 128) {
        s_w256[tid] = w256[tid];
        s_be2[tid] = be2[tid]; s_bc1[tid] = bc1[tid]; s_wc2[tid] = Wc2[tid];
    }
    __syncthreads();

#pragma unroll 2
    for (int t = wid; t < 64; t += 8) {
        int rnode = s_row[t], cnode = s_col[t];
        float4 p = __ldg((const float4*)(g_P + (size_t)rnode * 128) + lane);
        float4 q = __ldg((const float4*)(g_Q + (size_t)cnode * 128) + lane);
        float rad = s_rad[t];
        float4 w = *(const float4*)&s_w256[lane * 4];
        float v0 = silu_f(p.x + q.x + rad * w.x);
        float v1 = silu_f(p.y + q.y + rad * w.y);
        float v2 = silu_f(p.z + q.z + rad * w.z);
        float v3 = silu_f(p.w + q.w + rad * w.w);
        u32 h0 = bf16x2_rn(v0, v1), h1 = bf16x2_rn(v2, v3);
        int o = t * SH + lane * 2;
        *(uint2*)&hidH[o] = make_uint2(h0, h1);
        *(uint2*)&hidL[o] = make_uint2(bf16x2_lo(v0, v1, h0), bf16x2_lo(v2, v3, h1));
    }
    __syncthreads();

    float acc[2][4][4];

    // GEMM2: hid @ We2 (3-term, permuted columns)
    ZACC4(acc);
    mma3<8, 4>(hidHa, hidLa, SH, g_Bf2, acc, m0, ntb, lane);
#pragma unroll
    for (int mt = 0; mt < 2; mt++) {
        int ra = m0 + mt * 16 + g, rb = ra + 8;
        size_t na = (size_t)s_row[ra] * 128, nb = (size_t)s_row[rb] * 128;
#pragma unroll
        for (int j = 0; j < 2; j++) {
            int q  = (ntb >> 1) + j;
            int cb = 16 * q + 4 * tig;
            float b0 = s_be2[cb], b1 = s_be2[cb+1], b2 = s_be2[cb+2], b3 = s_be2[cb+3];
            float* A0 = acc[mt][2*j];
            float* A1 = acc[mt][2*j + 1];
            float r0 = silu_f(A0[0] + b0), r1 = silu_f(A0[1] + b1);
            float r2 = silu_f(A1[0] + b2), r3 = silu_f(A1[1] + b3);
            float s0 = silu_f(A0[2] + b0), s1 = silu_f(A0[3] + b1);
            float s2 = silu_f(A1[2] + b2), s3 = silu_f(A1[3] + b3);
            int u = 8 * q + 2 * tig;
            *(uint2*)&efH[ra * SH + u] = make_uint2(bf16x2_rn(r0, r1), bf16x2_rn(r2, r3));
            *(uint2*)&efH[rb * SH + u] = make_uint2(bf16x2_rn(s0, s1), bf16x2_rn(s2, s3));
            red_v4(&g_hagg[na + cb], make_float4(r0, r1, r2, r3));
            red_v4(&g_hagg[nb + cb], make_float4(s0, s1, s2, s3));
        }
    }
    __syncthreads();

    // GEMM3: ef @ Wc1 (1-term, coord path)
    ZACC4(acc);
    mma1t<8>(efHa, SH, g_Bf3, acc, m0, ntb, lane);
    {
        float p[4] = {0.f, 0.f, 0.f, 0.f};
#pragma unroll
        for (int mt = 0; mt < 2; mt++) {
#pragma unroll
            for (int nt = 0; nt < 4; nt++) {
                int col = (ntb + nt) * 8 + 2 * tig;
                float b0 = s_bc1[col], b1 = s_bc1[col + 1];
                float w0 = s_wc2[col], w1 = s_wc2[col + 1];
                p[mt*2+0] += silu_f(acc[mt][nt][0] + b0) * w0
                           + silu_f(acc[mt][nt][1] + b1) * w1;
                p[mt*2+1] += silu_f(acc[mt][nt][2] + b0) * w0
                           + silu_f(acc[mt][nt][3] + b1) * w1;
            }
        }
#pragma unroll
        for (int i = 0; i < 4; i++) {
            p[i] += __shfl_xor_sync(0xffffffffu, p[i], 1);
            p[i] += __shfl_xor_sync(0xffffffffu, p[i], 2);
        }
        if (tig == 0) {
#pragma unroll
            for (int mt = 0; mt < 2; mt++) {
                s_part[nw * 64 + m0 + mt * 16 + g]     = p[mt*2+0];
                s_part[nw * 64 + m0 + mt * 16 + g + 8] = p[mt*2+1];
            }
        }
    }
    __syncthreads();

    if (tid < 64) {
        float s = s_part[tid] + s_part[64 + tid] + s_part[128 + tid] + s_part[192 + tid];
        float4 v = make_float4(s_diff[tid*3+0] * s, s_diff[tid*3+1] * s,
                               s_diff[tid*3+2] * s, 1.0f);
        red_v4(&g_cagg4[s_row[tid] * 4], v);
    }
}

// ---------------- node kernel: 32 nodes/block, overlaid SMEM ----------------
#define NOFF_ALO 4224
#define NOFF_HL  2176     // hidH overlays A[0,2176), hidL at [2176,4352)
#define NOFF_MISC 8448
#define SMEM_NODE_BYTES ((NOFF_MISC + 256) * 4)

__global__ void __launch_bounds__(TE, 3)
node_mma_kernel(const float* __restrict__ h, const float* __restrict__ y,
                const float* __restrict__ bn1, const float* __restrict__ bn2,
                float* __restrict__ out_h, float* __restrict__ out_y)
{
    extern __shared__ u32 smu[];
    u32* AhiN = smu;
    u32* AloN = smu + NOFF_ALO;
    u32* hidH = smu;                 // overlay after GEMM1
    u32* hidL = smu + NOFF_HL;
    float* s_bn1 = (float*)(smu + NOFF_MISC);
    float* s_bn2 = s_bn1 + 128;

    const int tid  = threadIdx.x;
    const int lane = tid & 31;
    const int wid  = tid >> 5;
    const int g    = lane >> 2;
    const int tig  = lane & 3;
    const int ntb  = wid * 2;
    const int n0   = blockIdx.x * 32;

    const u32 smb = smem_u32(smu);
    const u32 AhiA = smb;
    const u32 AloA = smb + NOFF_ALO * 4;
    const u32 hHa  = smb;
    const u32 hLa  = smb + NOFF_HL * 4;

    if (tid < 128) { s_bn1[tid] = bn1[tid]; s_bn2[tid] = bn2[tid]; }

    // gather [h | hagg] (32 rows x 256) -> bf16 hi/lo, stride SHN
    for (int t = wid; t < 64; t += 8) {
        int r = t >> 1, half = t & 1, n = n0 + r;
        float4 v = make_float4(0.f, 0.f, 0.f, 0.f);
        if (n < N_NODES) {
            const float* src = half ? (g_hagg + (size_t)n * 128) : (h + (size_t)n * 128);
            v = __ldg((const float4*)src + lane);
        }
        u32 h0 = bf16x2_rn(v.x, v.y), h1 = bf16x2_rn(v.z, v.w);
        int o = r * SHN + half * 64 + lane * 2;
        *(uint2*)&AhiN[o] = make_uint2(h0, h1);
        *(uint2*)&AloN[o] = make_uint2(bf16x2_lo(v.x, v.y, h0), bf16x2_lo(v.z, v.w, h1));
    }
    __syncthreads();

    float acc[2][2][4];

    // GEMM1: [h|hagg] @ Wn1 (K=256, 3-term)
    ZACC2(acc);
    mma3<16, 2>(AhiA, AloA, SHN, g_Bfn1, acc, 0, ntb, lane);
    __syncthreads();   // A reads done before hid overlays A region
#pragma unroll
    for (int mt = 0; mt < 2; mt++) {
        int ra = mt * 16 + g, rb = ra + 8;
#pragma unroll
        for (int nt = 0; nt < 2; nt++) {
            int col = (ntb + nt) * 8 + 2 * tig;
            int uc  = (ntb + nt) * 4 + tig;
            float b0 = s_bn1[col], b1 = s_bn1[col + 1];
            float v0 = silu_f(acc[mt][nt][0] + b0), v1 = silu_f(acc[mt][nt][1] + b1);
            float v2 = silu_f(acc[mt][nt][2] + b0), v3 = silu_f(acc[mt][nt][3] + b1);
            u32 ha = bf16x2_rn(v0, v1), hb = bf16x2_rn(v2, v3);
            hidH[ra * SH + uc] = ha; hidL[ra * SH + uc] = bf16x2_lo(v0, v1, ha);
            hidH[rb * SH + uc] = hb; hidL[rb * SH + uc] = bf16x2_lo(v2, v3, hb);
        }
    }
    __syncthreads();

    // GEMM2: hid @ Wn2 (3-term) + bn2 + residual -> out_h
    ZACC2(acc);
    mma3<8, 2>(hHa, hLa, SH, g_Bfn2, acc, 0, ntb, lane);
#pragma unroll
    for (int mt = 0; mt < 2; mt++) {
        int ra = mt * 16 + g, rb = ra + 8;
        int na = n0 + ra, nb = n0 + rb;
#pragma unroll
        for (int nt = 0; nt < 2; nt++) {
            int col = (ntb + nt) * 8 + 2 * tig;
            float b0 = s_bn2[col], b1 = s_bn2[col + 1];
            if (na < N_NODES) {
                float2 hh = __ldg((const float2*)(h + (size_t)na * 128 + col));
                *(float2*)&out_h[(size_t)na * 128 + col] =
                    make_float2(acc[mt][nt][0] + b0 + hh.x, acc[mt][nt][1] + b1 + hh.y);
            }
            if (nb < N_NODES) {
                float2 hh = __ldg((const float2*)(h + (size_t)nb * 128 + col));
                *(float2*)&out_h[(size_t)nb * 128 + col] =
                    make_float2(acc[mt][nt][2] + b0 + hh.x, acc[mt][nt][3] + b1 + hh.y);
            }
        }
    }

    if (tid < 32) {
        int n = n0 + tid;
        if (n < N_NODES) {
            float c = g_cagg4[n * 4 + 3]; c = (c < 1.0f) ? 1.0f : c;
            out_y[n*3+0] = y[n*3+0] + g_cagg4[n*4+0] / c;
            out_y[n*3+1] = y[n*3+1] + g_cagg4[n*4+1] / c;
            out_y[n*3+2] = y[n*3+2] + g_cagg4[n*4+2] / c;
        }
    }
}

extern "C" void kernel_launch(void* const* d_in, const int* in_sizes, int n_in,
                              void* d_out, int out_size)
{
    const float* h   = (const float*)d_in[0];
    const float* y   = (const float*)d_in[1];
    const int*   ei  = (const int*)d_in[2];
    const float* We1 = (const float*)d_in[3];
    const float* be1 = (const float*)d_in[4];
    const float* We2 = (const float*)d_in[5];
    const float* be2 = (const float*)d_in[6];
    const float* Wc1 = (const float*)d_in[7];
    const float* bc1 = (const float*)d_in[8];
    const float* Wc2 = (const float*)d_in[9];
    const float* Wn1 = (const float*)d_in[10];
    const float* bn1 = (const float*)d_in[11];
    const float* Wn2 = (const float*)d_in[12];
    const float* bn2 = (const float*)d_in[13];

    float* out_h = (float*)d_out;
    float* out_y = out_h + (size_t)N_NODES * 128;

    cudaFuncSetAttribute(edge_kernel, cudaFuncAttributeMaxDynamicSharedMemorySize,
                         SMEM_EDGE_BYTES);
    cudaFuncSetAttribute(node_mma_kernel, cudaFuncAttributeMaxDynamicSharedMemorySize,
                         SMEM_NODE_BYTES);
    cudaFuncSetAttribute(pre_mma_kernel, cudaFuncAttributeMaxDynamicSharedMemorySize,
                         PRE_SMEM_BYTES);

    zp_kernel<<<624, TE>>>(We1, We2, Wc1, Wn1, Wn2);
    pre_mma_kernel<<<(N_NODES + 31) / 32, TE, PRE_SMEM_BYTES>>>(h, be1);

    edge_kernel<<<N_EDGES / 64, TE, SMEM_EDGE_BYTES>>>(
        y, ei, We1 + 256 * 128, be2, bc1, Wc2);

    node_mma_kernel<<<(N_NODES + 31) / 32, TE, SMEM_NODE_BYTES>>>(
        h, y, bn1, bn2, out_h, out_y);
}

// round 16
// speedup vs baseline: 1.5013x; 1.0797x over previous
#include <cuda_runtime.h>
#include <cstdint>

#define N_NODES 10000
#define N_EDGES 640000
#define TE 256

typedef uint32_t u32;

// ---------------- device scratch ----------------
__device__ float g_hagg[N_NODES * 128];
__device__ float g_cagg4[N_NODES * 4];
__device__ float g_P[N_NODES * 128];
__device__ float g_Q[N_NODES * 128];
__device__ uint4 g_Bf2[8 * 512];         // We2 hi/lo (column-permuted)
__device__ uint2 g_Bf3[8 * 512];         // Wc1 hi-only
__device__ uint4 g_Bfn1[16 * 512];       // Wn1 3-term (K=256)
__device__ uint4 g_Bfn2[8 * 512];        // Wn2 3-term
__device__ uint4 g_Bfp[8 * 512];         // We1[0:128] 3-term
__device__ uint4 g_Bfq[8 * 512];         // We1[128:256] 3-term

__device__ __forceinline__ float silu_f(float x) { return x / (1.0f + __expf(-x)); }

__device__ __forceinline__ u32 bf16x2_rn(float x0, float x1) {
    u32 r; asm("cvt.rn.bf16x2.f32 %0, %1, %2;" : "=r"(r) : "f"(x1), "f"(x0)); return r;
}
__device__ __forceinline__ u32 bf16x2_lo(float x0, float x1, u32 h) {
    float h0 = __uint_as_float(h << 16);
    float h1 = __uint_as_float(h & 0xffff0000u);
    return bf16x2_rn(x0 - h0, x1 - h1);
}
__device__ __forceinline__ u32 smem_u32(const void* p) {
    u32 a;
    asm("{ .reg .u64 t; cvta.to.shared.u64 t, %1; cvt.u32.u64 %0, t; }"
        : "=r"(a) : "l"(p));
    return a;
}
__device__ __forceinline__ void ldsm_x4(u32* r, u32 addr) {
    asm volatile("ldmatrix.sync.aligned.m8n8.x4.shared.b16 {%0,%1,%2,%3}, [%4];"
        : "=r"(r[0]), "=r"(r[1]), "=r"(r[2]), "=r"(r[3]) : "r"(addr));
}
__device__ __forceinline__ void red_v4(float* p, float4 v) {
    asm volatile("red.global.add.v4.f32 [%0], {%1,%2,%3,%4};"
        :: "l"(p), "f"(v.x), "f"(v.y), "f"(v.z), "f"(v.w) : "memory");
}

#define MMA_BF16(d, a0, a1, a2, a3, b0, b1)                                 \
    asm volatile(                                                           \
        "mma.sync.aligned.m16n8k16.row.col.f32.bf16.bf16.f32 "              \
        "{%0,%1,%2,%3},{%4,%5,%6,%7},{%8,%9},{%0,%1,%2,%3};"                \
        : "+f"((d)[0]), "+f"((d)[1]), "+f"((d)[2]), "+f"((d)[3])            \
        : "r"(a0), "r"(a1), "r"(a2), "r"(a3), "r"(b0), "r"(b1))

// ---------------- zero + weight-fragment prep (merged) ----------------
__global__ void zp_kernel(const float* __restrict__ We1,
                          const float* __restrict__ We2,
                          const float* __restrict__ Wc1,
                          const float* __restrict__ Wn1,
                          const float* __restrict__ Wn2)
{
    if (blockIdx.x >= 112) {
        int i = (blockIdx.x - 112) * blockDim.x + threadIdx.x;
        int st = 512 * blockDim.x;
        for (int k = i; k < N_NODES * 128; k += st) g_hagg[k] = 0.0f;
        for (int k = i; k < N_NODES * 4;   k += st) g_cagg4[k] = 0.0f;
        return;
    }
    int i = blockIdx.x * blockDim.x + threadIdx.x;
    const float* W; int idx, mode;
    if (i < 4096)        { W = We2; idx = i;         mode = 0; }
    else if (i < 8192)   { W = Wc1; idx = i - 4096;  mode = 1; }
    else if (i < 16384)  { W = Wn1; idx = i - 8192;  mode = 2; }
    else if (i < 20480)  { W = Wn2; idx = i - 16384; mode = 3; }
    else if (i < 24576)  { W = We1;             idx = i - 20480; mode = 4; }
    else                 { W = We1 + 128 * 128; idx = i - 24576; mode = 5; }

    int c = idx >> 9, rem = idx & 511;
    int t = rem >> 5, l = rem & 31;
    int g = l >> 2, tig = l & 3;
    int n;
    if (mode == 0) {
        n = 16 * (t >> 1) + 4 * (g >> 1) + 2 * (t & 1) + (g & 1);
    } else {
        n = t * 8 + g;
    }
    int k0 = c * 16 + 2 * tig;
    float w0 = W[(k0    ) * 128 + n];
    float w1 = W[(k0 + 1) * 128 + n];
    float w2 = W[(k0 + 8) * 128 + n];
    float w3 = W[(k0 + 9) * 128 + n];
    u32 bh01 = bf16x2_rn(w0, w1), bh23 = bf16x2_rn(w2, w3);
    u32 bl01 = bf16x2_lo(w0, w1, bh01), bl23 = bf16x2_lo(w2, w3, bh23);
    uint4 v4 = make_uint4(bh01, bh23, bl01, bl23);
    if (mode == 0)      g_Bf2[idx]  = v4;
    else if (mode == 1) g_Bf3[idx]  = make_uint2(bh01, bh23);
    else if (mode == 2) g_Bfn1[idx] = v4;
    else if (mode == 3) g_Bfn2[idx] = v4;
    else if (mode == 4) g_Bfp[idx]  = v4;
    else                g_Bfq[idx]  = v4;
}

// ---------------- bf16 mma cores ----------------
// 3-term: Ah*Bh + Al*Bh + Ah*Bl
template<int KC, int NT>
__device__ __forceinline__ void mma3(
    u32 AhiA, u32 AloA, int SA,
    const uint4* __restrict__ Bf, float acc[2][NT][4],
    int m0, int ntb, int lane)
{
    int arow = (m0 + (lane & 15)) * SA + ((lane >> 4) << 2);
    u32 h0 = AhiA + arow * 4, h1 = h0 + 16 * SA * 4;
    u32 l0 = AloA + arow * 4, l1 = l0 + 16 * SA * 4;
#pragma unroll
    for (int c = 0; c < KC; c++) {
        uint4 bf[NT];
#pragma unroll
        for (int nt = 0; nt < NT; nt++)
            bf[nt] = __ldg(Bf + (c * 16 + ntb + nt) * 32 + lane);
        u32 ah[2][4], al[2][4];
        ldsm_x4(ah[0], h0 + c * 32);
        ldsm_x4(ah[1], h1 + c * 32);
        ldsm_x4(al[0], l0 + c * 32);
        ldsm_x4(al[1], l1 + c * 32);
#pragma unroll
        for (int nt = 0; nt < NT; nt++) {
#pragma unroll
            for (int mt = 0; mt < 2; mt++) {
                MMA_BF16(acc[mt][nt], ah[mt][0], ah[mt][1], ah[mt][2], ah[mt][3],
                         bf[nt].x, bf[nt].y);
                MMA_BF16(acc[mt][nt], al[mt][0], al[mt][1], al[mt][2], al[mt][3],
                         bf[nt].x, bf[nt].y);
                MMA_BF16(acc[mt][nt], ah[mt][0], ah[mt][1], ah[mt][2], ah[mt][3],
                         bf[nt].z, bf[nt].w);
            }
        }
    }
}

// 2-term: Ah*Bh + Ah*Bl (A hi only; B hi+lo from uint4 fragments)
template<int KC, int NT>
__device__ __forceinline__ void mma2a(
    u32 AhiA, int SA,
    const uint4* __restrict__ Bf, float acc[2][NT][4],
    int m0, int ntb, int lane)
{
    int arow = (m0 + (lane & 15)) * SA + ((lane >> 4) << 2);
    u32 h0 = AhiA + arow * 4, h1 = h0 + 16 * SA * 4;
#pragma unroll
    for (int c = 0; c < KC; c++) {
        uint4 bf[NT];
#pragma unroll
        for (int nt = 0; nt < NT; nt++)
            bf[nt] = __ldg(Bf + (c * 16 + ntb + nt) * 32 + lane);
        u32 ah[2][4];
        ldsm_x4(ah[0], h0 + c * 32);
        ldsm_x4(ah[1], h1 + c * 32);
#pragma unroll
        for (int nt = 0; nt < NT; nt++) {
#pragma unroll
            for (int mt = 0; mt < 2; mt++) {
                MMA_BF16(acc[mt][nt], ah[mt][0], ah[mt][1], ah[mt][2], ah[mt][3],
                         bf[nt].x, bf[nt].y);
                MMA_BF16(acc[mt][nt], ah[mt][0], ah[mt][1], ah[mt][2], ah[mt][3],
                         bf[nt].z, bf[nt].w);
            }
        }
    }
}

// 1-term: Ah*Bh
template<int KC>
__device__ __forceinline__ void mma1t(
    u32 AhiA, int SA,
    const uint2* __restrict__ Bf, float acc[2][4][4],
    int m0, int ntb, int lane)
{
    int arow = (m0 + (lane & 15)) * SA + ((lane >> 4) << 2);
    u32 h0 = AhiA + arow * 4, h1 = h0 + 16 * SA * 4;
#pragma unroll
    for (int c = 0; c < KC; c++) {
        uint2 bf[4];
#pragma unroll
        for (int nt = 0; nt < 4; nt++)
            bf[nt] = __ldg(Bf + (c * 16 + ntb + nt) * 32 + lane);
        u32 ah[2][4];
        ldsm_x4(ah[0], h0 + c * 32);
        ldsm_x4(ah[1], h1 + c * 32);
#pragma unroll
        for (int nt = 0; nt < 4; nt++) {
#pragma unroll
            for (int mt = 0; mt < 2; mt++) {
                MMA_BF16(acc[mt][nt], ah[mt][0], ah[mt][1], ah[mt][2], ah[mt][3],
                         bf[nt].x, bf[nt].y);
            }
        }
    }
}

#define ZACC4(acc) do { _Pragma("unroll") for (int a_ = 0; a_ < 2; a_++) \
    _Pragma("unroll") for (int b_ = 0; b_ < 4; b_++) \
    _Pragma("unroll") for (int c_ = 0; c_ < 4; c_++) acc[a_][b_][c_] = 0.0f; } while (0)
#define ZACC2(acc) do { _Pragma("unroll") for (int a_ = 0; a_ < 2; a_++) \
    _Pragma("unroll") for (int b_ = 0; b_ < 2; b_++) \
    _Pragma("unroll") for (int c_ = 0; c_ < 4; c_++) acc[a_][b_][c_] = 0.0f; } while (0)

#define SH 68
#define SHN 132

// ---------------- pre: P/Q = h @ We1 halves, 32 nodes/block ----------------
#define POFF_ALO 4224
#define POFF_MISC 8448
#define PRE_SMEM_BYTES ((POFF_MISC + 128) * 4)

__global__ void __launch_bounds__(TE, 3)
pre_mma_kernel(const float* __restrict__ h, const float* __restrict__ be1)
{
    extern __shared__ u32 smu[];
    u32* Ahi = smu;
    u32* Alo = smu + POFF_ALO;
    float* s_be1 = (float*)(smu + POFF_MISC);

    const int tid  = threadIdx.x;
    const int lane = tid & 31;
    const int wid  = tid >> 5;
    const int g    = lane >> 2;
    const int tig  = lane & 3;
    const int ntb  = wid * 2;
    const int n0   = blockIdx.x * 32;

    const u32 smb = smem_u32(smu);
    const u32 AhiA = smb;
    const u32 AloA = smb + POFF_ALO * 4;

    if (tid < 128) s_be1[tid] = be1[tid];

    for (int r = wid * 4; r < wid * 4 + 4; r++) {
        int n = n0 + r;
        float4 v = make_float4(0.f, 0.f, 0.f, 0.f);
        if (n < N_NODES) v = __ldg((const float4*)(h + (size_t)n * 128) + lane);
        u32 h0 = bf16x2_rn(v.x, v.y), h1 = bf16x2_rn(v.z, v.w);
        int o = r * SH + lane * 2;
        *(uint2*)&Ahi[o] = make_uint2(h0, h1);
        *(uint2*)&Alo[o] = make_uint2(bf16x2_lo(v.x, v.y, h0), bf16x2_lo(v.z, v.w, h1));
    }
    __syncthreads();

    float acc[2][2][4];

    ZACC2(acc);
    mma3<8, 2>(AhiA, AloA, SH, g_Bfp, acc, 0, ntb, lane);
#pragma unroll
    for (int mt = 0; mt < 2; mt++) {
        int ra = mt * 16 + g, rb = ra + 8;
        int na = n0 + ra, nb = n0 + rb;
#pragma unroll
        for (int nt = 0; nt < 2; nt++) {
            int col = (ntb + nt) * 8 + 2 * tig;
            float b0 = s_be1[col], b1 = s_be1[col + 1];
            if (na < N_NODES)
                *(float2*)&g_P[(size_t)na * 128 + col] =
                    make_float2(acc[mt][nt][0] + b0, acc[mt][nt][1] + b1);
            if (nb < N_NODES)
                *(float2*)&g_P[(size_t)nb * 128 + col] =
                    make_float2(acc[mt][nt][2] + b0, acc[mt][nt][3] + b1);
        }
    }

    ZACC2(acc);
    mma3<8, 2>(AhiA, AloA, SH, g_Bfq, acc, 0, ntb, lane);
#pragma unroll
    for (int mt = 0; mt < 2; mt++) {
        int ra = mt * 16 + g, rb = ra + 8;
        int na = n0 + ra, nb = n0 + rb;
#pragma unroll
        for (int nt = 0; nt < 2; nt++) {
            int col = (ntb + nt) * 8 + 2 * tig;
            if (na < N_NODES)
                *(float2*)&g_Q[(size_t)na * 128 + col] =
                    make_float2(acc[mt][nt][0], acc[mt][nt][1]);
            if (nb < N_NODES)
                *(float2*)&g_Q[(size_t)nb * 128 + col] =
                    make_float2(acc[mt][nt][2], acc[mt][nt][3]);
        }
    }
}

// ---------------- edge kernel: hid bf16-hi only, 2-term GEMM2 ----------------
#define OFF_HIDH 0
#define OFF_EFH  4352
#define OFF_MISC 8704
#define SMEM_EDGE_U32 (OFF_MISC + 1152)
#define SMEM_EDGE_BYTES (SMEM_EDGE_U32 * 4)

__global__ void __launch_bounds__(TE, 3)
edge_kernel(const float* __restrict__ y, const int* __restrict__ ei,
            const float* __restrict__ w256,
            const float* __restrict__ be2, const float* __restrict__ bc1,
            const float* __restrict__ Wc2)
{
    extern __shared__ u32 smu[];
    u32* hidH = smu + OFF_HIDH;
    u32* efH  = smu + OFF_EFH;
    float* s_w256 = (float*)(smu + OFF_MISC);
    float* s_be2  = s_w256 + 128;
    float* s_bc1  = s_be2 + 128;
    float* s_wc2  = s_bc1 + 128;
    float* s_rad  = s_wc2 + 128;
    float* s_diff = s_rad + 64;
    float* s_part = s_diff + 192;
    int*   s_row  = (int*)(s_part + 256);
    int*   s_col  = s_row + 64;

    const int tid  = threadIdx.x;
    const int lane = tid & 31;
    const int wid  = tid >> 5;
    const int g    = lane >> 2;
    const int tig  = lane & 3;
    const int mw   = wid >> 2;
    const int nw   = wid & 3;
    const int m0   = mw * 32;
    const int ntb  = nw * 4;
    const int e0g  = blockIdx.x * 64;

    const u32 smb   = smem_u32(smu);
    const u32 hidHa = smb + OFF_HIDH * 4;
    const u32 efHa  = smb + OFF_EFH * 4;

    if (tid < 64) {
        int r = ei[e0g + tid], c = ei[N_EDGES + e0g + tid];
        s_row[tid] = r; s_col[tid] = c;
        float dx = y[r*3+0]-y[c*3+0], dy = y[r*3+1]-y[c*3+1], dz = y[r*3+2]-y[c*3+2];
        s_diff[tid*3+0] = dx; s_diff[tid*3+1] = dy; s_diff[tid*3+2] = dz;
        s_rad[tid] = dx*dx + dy*dy + dz*dz;
    }
    if (tid < 128) {
        s_w256[tid] = w256[tid];
        s_be2[tid] = be2[tid]; s_bc1[tid] = bc1[tid]; s_wc2[tid] = Wc2[tid];
    }
    __syncthreads();

    // ---- fused former-GEMM1: hid = silu(P[row] + Q[col] + rad*w256), hi only ----
#pragma unroll 2
    for (int t = wid; t < 64; t += 8) {
        int rnode = s_row[t], cnode = s_col[t];
        float4 p = __ldg((const float4*)(g_P + (size_t)rnode * 128) + lane);
        float4 q = __ldg((const float4*)(g_Q + (size_t)cnode * 128) + lane);
        float rad = s_rad[t];
        float4 w = *(const float4*)&s_w256[lane * 4];
        float v0 = silu_f(p.x + q.x + rad * w.x);
        float v1 = silu_f(p.y + q.y + rad * w.y);
        float v2 = silu_f(p.z + q.z + rad * w.z);
        float v3 = silu_f(p.w + q.w + rad * w.w);
        int o = t * SH + lane * 2;
        *(uint2*)&hidH[o] = make_uint2(bf16x2_rn(v0, v1), bf16x2_rn(v2, v3));
    }
    __syncthreads();

    float acc[2][4][4];

    // ---- GEMM2: hid @ We2 (2-term: Ah*Bh + Ah*Bl, permuted columns) ----
    ZACC4(acc);
    mma2a<8, 4>(hidHa, SH, g_Bf2, acc, m0, ntb, lane);
#pragma unroll
    for (int mt = 0; mt < 2; mt++) {
        int ra = m0 + mt * 16 + g, rb = ra + 8;
        size_t na = (size_t)s_row[ra] * 128, nb = (size_t)s_row[rb] * 128;
#pragma unroll
        for (int j = 0; j < 2; j++) {
            int q  = (ntb >> 1) + j;
            int cb = 16 * q + 4 * tig;
            float b0 = s_be2[cb], b1 = s_be2[cb+1], b2 = s_be2[cb+2], b3 = s_be2[cb+3];
            float* A0 = acc[mt][2*j];
            float* A1 = acc[mt][2*j + 1];
            float r0 = silu_f(A0[0] + b0), r1 = silu_f(A0[1] + b1);
            float r2 = silu_f(A1[0] + b2), r3 = silu_f(A1[1] + b3);
            float s0 = silu_f(A0[2] + b0), s1 = silu_f(A0[3] + b1);
            float s2 = silu_f(A1[2] + b2), s3 = silu_f(A1[3] + b3);
            int u = 8 * q + 2 * tig;
            *(uint2*)&efH[ra * SH + u] = make_uint2(bf16x2_rn(r0, r1), bf16x2_rn(r2, r3));
            *(uint2*)&efH[rb * SH + u] = make_uint2(bf16x2_rn(s0, s1), bf16x2_rn(s2, s3));
            red_v4(&g_hagg[na + cb], make_float4(r0, r1, r2, r3));
            red_v4(&g_hagg[nb + cb], make_float4(s0, s1, s2, s3));
        }
    }
    __syncthreads();

    // ---- GEMM3: ef @ Wc1 (1-term, coord path) ----
    ZACC4(acc);
    mma1t<8>(efHa, SH, g_Bf3, acc, m0, ntb, lane);
    {
        float p[4] = {0.f, 0.f, 0.f, 0.f};
#pragma unroll
        for (int mt = 0; mt < 2; mt++) {
#pragma unroll
            for (int nt = 0; nt < 4; nt++) {
                int col = (ntb + nt) * 8 + 2 * tig;
                float b0 = s_bc1[col], b1 = s_bc1[col + 1];
                float w0 = s_wc2[col], w1 = s_wc2[col + 1];
                p[mt*2+0] += silu_f(acc[mt][nt][0] + b0) * w0
                           + silu_f(acc[mt][nt][1] + b1) * w1;
                p[mt*2+1] += silu_f(acc[mt][nt][2] + b0) * w0
                           + silu_f(acc[mt][nt][3] + b1) * w1;
            }
        }
#pragma unroll
        for (int i = 0; i < 4; i++) {
            p[i] += __shfl_xor_sync(0xffffffffu, p[i], 1);
            p[i] += __shfl_xor_sync(0xffffffffu, p[i], 2);
        }
        if (tig == 0) {
#pragma unroll
            for (int mt = 0; mt < 2; mt++) {
                s_part[nw * 64 + m0 + mt * 16 + g]     = p[mt*2+0];
                s_part[nw * 64 + m0 + mt * 16 + g + 8] = p[mt*2+1];
            }
        }
    }
    __syncthreads();

    if (tid < 64) {
        float s = s_part[tid] + s_part[64 + tid] + s_part[128 + tid] + s_part[192 + tid];
        float4 v = make_float4(s_diff[tid*3+0] * s, s_diff[tid*3+1] * s,
                               s_diff[tid*3+2] * s, 1.0f);
        red_v4(&g_cagg4[s_row[tid] * 4], v);
    }
}

// ---------------- node kernel: 32 nodes/block, overlaid SMEM ----------------
#define NOFF_ALO 4224
#define NOFF_HL  2176
#define NOFF_MISC 8448
#define SMEM_NODE_BYTES ((NOFF_MISC + 256) * 4)

__global__ void __launch_bounds__(TE, 3)
node_mma_kernel(const float* __restrict__ h, const float* __restrict__ y,
                const float* __restrict__ bn1, const float* __restrict__ bn2,
                float* __restrict__ out_h, float* __restrict__ out_y)
{
    extern __shared__ u32 smu[];
    u32* AhiN = smu;
    u32* AloN = smu + NOFF_ALO;
    u32* hidH = smu;
    u32* hidL = smu + NOFF_HL;
    float* s_bn1 = (float*)(smu + NOFF_MISC);
    float* s_bn2 = s_bn1 + 128;

    const int tid  = threadIdx.x;
    const int lane = tid & 31;
    const int wid  = tid >> 5;
    const int g    = lane >> 2;
    const int tig  = lane & 3;
    const int ntb  = wid * 2;
    const int n0   = blockIdx.x * 32;

    const u32 smb = smem_u32(smu);
    const u32 AhiA = smb;
    const u32 AloA = smb + NOFF_ALO * 4;
    const u32 hHa  = smb;
    const u32 hLa  = smb + NOFF_HL * 4;

    if (tid < 128) { s_bn1[tid] = bn1[tid]; s_bn2[tid] = bn2[tid]; }

    for (int t = wid; t < 64; t += 8) {
        int r = t >> 1, half = t & 1, n = n0 + r;
        float4 v = make_float4(0.f, 0.f, 0.f, 0.f);
        if (n < N_NODES) {
            const float* src = half ? (g_hagg + (size_t)n * 128) : (h + (size_t)n * 128);
            v = __ldg((const float4*)src + lane);
        }
        u32 h0 = bf16x2_rn(v.x, v.y), h1 = bf16x2_rn(v.z, v.w);
        int o = r * SHN + half * 64 + lane * 2;
        *(uint2*)&AhiN[o] = make_uint2(h0, h1);
        *(uint2*)&AloN[o] = make_uint2(bf16x2_lo(v.x, v.y, h0), bf16x2_lo(v.z, v.w, h1));
    }
    __syncthreads();

    float acc[2][2][4];

    ZACC2(acc);
    mma3<16, 2>(AhiA, AloA, SHN, g_Bfn1, acc, 0, ntb, lane);
    __syncthreads();
#pragma unroll
    for (int mt = 0; mt < 2; mt++) {
        int ra = mt * 16 + g, rb = ra + 8;
#pragma unroll
        for (int nt = 0; nt < 2; nt++) {
            int col = (ntb + nt) * 8 + 2 * tig;
            int uc  = (ntb + nt) * 4 + tig;
            float b0 = s_bn1[col], b1 = s_bn1[col + 1];
            float v0 = silu_f(acc[mt][nt][0] + b0), v1 = silu_f(acc[mt][nt][1] + b1);
            float v2 = silu_f(acc[mt][nt][2] + b0), v3 = silu_f(acc[mt][nt][3] + b1);
            u32 ha = bf16x2_rn(v0, v1), hb = bf16x2_rn(v2, v3);
            hidH[ra * SH + uc] = ha; hidL[ra * SH + uc] = bf16x2_lo(v0, v1, ha);
            hidH[rb * SH + uc] = hb; hidL[rb * SH + uc] = bf16x2_lo(v2, v3, hb);
        }
    }
    __syncthreads();

    ZACC2(acc);
    mma3<8, 2>(hHa, hLa, SH, g_Bfn2, acc, 0, ntb, lane);
#pragma unroll
    for (int mt = 0; mt < 2; mt++) {
        int ra = mt * 16 + g, rb = ra + 8;
        int na = n0 + ra, nb = n0 + rb;
#pragma unroll
        for (int nt = 0; nt < 2; nt++) {
            int col = (ntb + nt) * 8 + 2 * tig;
            float b0 = s_bn2[col], b1 = s_bn2[col + 1];
            if (na < N_NODES) {
                float2 hh = __ldg((const float2*)(h + (size_t)na * 128 + col));
                *(float2*)&out_h[(size_t)na * 128 + col] =
                    make_float2(acc[mt][nt][0] + b0 + hh.x, acc[mt][nt][1] + b1 + hh.y);
            }
            if (nb < N_NODES) {
                float2 hh = __ldg((const float2*)(h + (size_t)nb * 128 + col));
                *(float2*)&out_h[(size_t)nb * 128 + col] =
                    make_float2(acc[mt][nt][2] + b0 + hh.x, acc[mt][nt][3] + b1 + hh.y);
            }
        }
    }

    if (tid < 32) {
        int n = n0 + tid;
        if (n < N_NODES) {
            float c = g_cagg4[n * 4 + 3]; c = (c < 1.0f) ? 1.0f : c;
            out_y[n*3+0] = y[n*3+0] + g_cagg4[n*4+0] / c;
            out_y[n*3+1] = y[n*3+1] + g_cagg4[n*4+1] / c;
            out_y[n*3+2] = y[n*3+2] + g_cagg4[n*4+2] / c;
        }
    }
}

extern "C" void kernel_launch(void* const* d_in, const int* in_sizes, int n_in,
                              void* d_out, int out_size)
{
    const float* h   = (const float*)d_in[0];
    const float* y   = (const float*)d_in[1];
    const int*   ei  = (const int*)d_in[2];
    const float* We1 = (const float*)d_in[3];
    const float* be1 = (const float*)d_in[4];
    const float* We2 = (const float*)d_in[5];
    const float* be2 = (const float*)d_in[6];
    const float* Wc1 = (const float*)d_in[7];
    const float* bc1 = (const float*)d_in[8];
    const float* Wc2 = (const float*)d_in[9];
    const float* Wn1 = (const float*)d_in[10];
    const float* bn1 = (const float*)d_in[11];
    const float* Wn2 = (const float*)d_in[12];
    const float* bn2 = (const float*)d_in[13];

    float* out_h = (float*)d_out;
    float* out_y = out_h + (size_t)N_NODES * 128;

    cudaFuncSetAttribute(edge_kernel, cudaFuncAttributeMaxDynamicSharedMemorySize,
                         SMEM_EDGE_BYTES);
    cudaFuncSetAttribute(node_mma_kernel, cudaFuncAttributeMaxDynamicSharedMemorySize,
                         SMEM_NODE_BYTES);
    cudaFuncSetAttribute(pre_mma_kernel, cudaFuncAttributeMaxDynamicSharedMemorySize,
                         PRE_SMEM_BYTES);

    zp_kernel<<<624, TE>>>(We1, We2, Wc1, Wn1, Wn2);
    pre_mma_kernel<<<(N_NODES + 31) / 32, TE, PRE_SMEM_BYTES>>>(h, be1);

    edge_kernel<<<N_EDGES / 64, TE, SMEM_EDGE_BYTES>>>(
        y, ei, We1 + 256 * 128, be2, bc1, Wc2);

    node_mma_kernel<<<(N_NODES + 31) / 32, TE, SMEM_NODE_BYTES>>>(
        h, y, bn1, bn2, out_h, out_y);
}

// round 17
// speedup vs baseline: 1.6695x; 1.1121x over previous
#include <cuda_runtime.h>
#include <cstdint>

#define N_NODES 10000
#define N_EDGES 640000
#define TE 256
#define TEE 128

typedef uint32_t u32;

// ---------------- device scratch ----------------
__device__ float g_hagg[N_NODES * 128];
__device__ float g_cagg4[N_NODES * 4];
__device__ float g_P[N_NODES * 128];
__device__ float g_Q[N_NODES * 128];
__device__ uint4 g_Bf2[8 * 512];         // We2 hi/lo (column-permuted)
__device__ uint2 g_Bf3[8 * 512];         // Wc1 hi-only
__device__ uint4 g_Bfn1[16 * 512];       // Wn1 3-term (K=256)
__device__ uint4 g_Bfn2[8 * 512];        // Wn2 3-term
__device__ uint4 g_Bfp[8 * 512];         // We1[0:128] 3-term
__device__ uint4 g_Bfq[8 * 512];         // We1[128:256] 3-term

__device__ __forceinline__ float silu_f(float x) { return x / (1.0f + __expf(-x)); }

__device__ __forceinline__ u32 bf16x2_rn(float x0, float x1) {
    u32 r; asm("cvt.rn.bf16x2.f32 %0, %1, %2;" : "=r"(r) : "f"(x1), "f"(x0)); return r;
}
__device__ __forceinline__ u32 bf16x2_lo(float x0, float x1, u32 h) {
    float h0 = __uint_as_float(h << 16);
    float h1 = __uint_as_float(h & 0xffff0000u);
    return bf16x2_rn(x0 - h0, x1 - h1);
}
__device__ __forceinline__ u32 smem_u32(const void* p) {
    u32 a;
    asm("{ .reg .u64 t; cvta.to.shared.u64 t, %1; cvt.u32.u64 %0, t; }"
        : "=r"(a) : "l"(p));
    return a;
}
__device__ __forceinline__ void ldsm_x4(u32* r, u32 addr) {
    asm volatile("ldmatrix.sync.aligned.m8n8.x4.shared.b16 {%0,%1,%2,%3}, [%4];"
        : "=r"(r[0]), "=r"(r[1]), "=r"(r[2]), "=r"(r[3]) : "r"(addr));
}
__device__ __forceinline__ void red_v4(float* p, float4 v) {
    asm volatile("red.global.add.v4.f32 [%0], {%1,%2,%3,%4};"
        :: "l"(p), "f"(v.x), "f"(v.y), "f"(v.z), "f"(v.w) : "memory");
}

#define MMA_BF16(d, a0, a1, a2, a3, b0, b1)                                 \
    asm volatile(                                                           \
        "mma.sync.aligned.m16n8k16.row.col.f32.bf16.bf16.f32 "              \
        "{%0,%1,%2,%3},{%4,%5,%6,%7},{%8,%9},{%0,%1,%2,%3};"                \
        : "+f"((d)[0]), "+f"((d)[1]), "+f"((d)[2]), "+f"((d)[3])            \
        : "r"(a0), "r"(a1), "r"(a2), "r"(a3), "r"(b0), "r"(b1))

// ---------------- zero + weight-fragment prep (merged) ----------------
__global__ void zp_kernel(const float* __restrict__ We1,
                          const float* __restrict__ We2,
                          const float* __restrict__ Wc1,
                          const float* __restrict__ Wn1,
                          const float* __restrict__ Wn2)
{
    if (blockIdx.x >= 112) {
        int i = (blockIdx.x - 112) * blockDim.x + threadIdx.x;
        int st = 512 * blockDim.x;
        for (int k = i; k < N_NODES * 128; k += st) g_hagg[k] = 0.0f;
        for (int k = i; k < N_NODES * 4;   k += st) g_cagg4[k] = 0.0f;
        return;
    }
    int i = blockIdx.x * blockDim.x + threadIdx.x;
    const float* W; int idx, mode;
    if (i < 4096)        { W = We2; idx = i;         mode = 0; }
    else if (i < 8192)   { W = Wc1; idx = i - 4096;  mode = 1; }
    else if (i < 16384)  { W = Wn1; idx = i - 8192;  mode = 2; }
    else if (i < 20480)  { W = Wn2; idx = i - 16384; mode = 3; }
    else if (i < 24576)  { W = We1;             idx = i - 20480; mode = 4; }
    else                 { W = We1 + 128 * 128; idx = i - 24576; mode = 5; }

    int c = idx >> 9, rem = idx & 511;
    int t = rem >> 5, l = rem & 31;
    int g = l >> 2, tig = l & 3;
    int n;
    if (mode == 0) {
        n = 16 * (t >> 1) + 4 * (g >> 1) + 2 * (t & 1) + (g & 1);
    } else {
        n = t * 8 + g;
    }
    int k0 = c * 16 + 2 * tig;
    float w0 = W[(k0    ) * 128 + n];
    float w1 = W[(k0 + 1) * 128 + n];
    float w2 = W[(k0 + 8) * 128 + n];
    float w3 = W[(k0 + 9) * 128 + n];
    u32 bh01 = bf16x2_rn(w0, w1), bh23 = bf16x2_rn(w2, w3);
    u32 bl01 = bf16x2_lo(w0, w1, bh01), bl23 = bf16x2_lo(w2, w3, bh23);
    uint4 v4 = make_uint4(bh01, bh23, bl01, bl23);
    if (mode == 0)      g_Bf2[idx]  = v4;
    else if (mode == 1) g_Bf3[idx]  = make_uint2(bh01, bh23);
    else if (mode == 2) g_Bfn1[idx] = v4;
    else if (mode == 3) g_Bfn2[idx] = v4;
    else if (mode == 4) g_Bfp[idx]  = v4;
    else                g_Bfq[idx]  = v4;
}

// ---------------- bf16 mma cores ----------------
template<int KC, int NT>
__device__ __forceinline__ void mma3(
    u32 AhiA, u32 AloA, int SA,
    const uint4* __restrict__ Bf, float acc[2][NT][4],
    int m0, int ntb, int lane)
{
    int arow = (m0 + (lane & 15)) * SA + ((lane >> 4) << 2);
    u32 h0 = AhiA + arow * 4, h1 = h0 + 16 * SA * 4;
    u32 l0 = AloA + arow * 4, l1 = l0 + 16 * SA * 4;
#pragma unroll
    for (int c = 0; c < KC; c++) {
        uint4 bf[NT];
#pragma unroll
        for (int nt = 0; nt < NT; nt++)
            bf[nt] = __ldg(Bf + (c * 16 + ntb + nt) * 32 + lane);
        u32 ah[2][4], al[2][4];
        ldsm_x4(ah[0], h0 + c * 32);
        ldsm_x4(ah[1], h1 + c * 32);
        ldsm_x4(al[0], l0 + c * 32);
        ldsm_x4(al[1], l1 + c * 32);
#pragma unroll
        for (int nt = 0; nt < NT; nt++) {
#pragma unroll
            for (int mt = 0; mt < 2; mt++) {
                MMA_BF16(acc[mt][nt], ah[mt][0], ah[mt][1], ah[mt][2], ah[mt][3],
                         bf[nt].x, bf[nt].y);
                MMA_BF16(acc[mt][nt], al[mt][0], al[mt][1], al[mt][2], al[mt][3],
                         bf[nt].x, bf[nt].y);
                MMA_BF16(acc[mt][nt], ah[mt][0], ah[mt][1], ah[mt][2], ah[mt][3],
                         bf[nt].z, bf[nt].w);
            }
        }
    }
}

// 2-term: Ah*Bh + Ah*Bl
template<int KC, int NT>
__device__ __forceinline__ void mma2a(
    u32 AhiA, int SA,
    const uint4* __restrict__ Bf, float acc[2][NT][4],
    int m0, int ntb, int lane)
{
    int arow = (m0 + (lane & 15)) * SA + ((lane >> 4) << 2);
    u32 h0 = AhiA + arow * 4, h1 = h0 + 16 * SA * 4;
#pragma unroll
    for (int c = 0; c < KC; c++) {
        uint4 bf[NT];
#pragma unroll
        for (int nt = 0; nt < NT; nt++)
            bf[nt] = __ldg(Bf + (c * 16 + ntb + nt) * 32 + lane);
        u32 ah[2][4];
        ldsm_x4(ah[0], h0 + c * 32);
        ldsm_x4(ah[1], h1 + c * 32);
#pragma unroll
        for (int nt = 0; nt < NT; nt++) {
#pragma unroll
            for (int mt = 0; mt < 2; mt++) {
                MMA_BF16(acc[mt][nt], ah[mt][0], ah[mt][1], ah[mt][2], ah[mt][3],
                         bf[nt].x, bf[nt].y);
                MMA_BF16(acc[mt][nt], ah[mt][0], ah[mt][1], ah[mt][2], ah[mt][3],
                         bf[nt].z, bf[nt].w);
            }
        }
    }
}

// 1-term: Ah*Bh
template<int KC>
__device__ __forceinline__ void mma1t(
    u32 AhiA, int SA,
    const uint2* __restrict__ Bf, float acc[2][4][4],
    int m0, int ntb, int lane)
{
    int arow = (m0 + (lane & 15)) * SA + ((lane >> 4) << 2);
    u32 h0 = AhiA + arow * 4, h1 = h0 + 16 * SA * 4;
#pragma unroll
    for (int c = 0; c < KC; c++) {
        uint2 bf[4];
#pragma unroll
        for (int nt = 0; nt < 4; nt++)
            bf[nt] = __ldg(Bf + (c * 16 + ntb + nt) * 32 + lane);
        u32 ah[2][4];
        ldsm_x4(ah[0], h0 + c * 32);
        ldsm_x4(ah[1], h1 + c * 32);
#pragma unroll
        for (int nt = 0; nt < 4; nt++) {
#pragma unroll
            for (int mt = 0; mt < 2; mt++) {
                MMA_BF16(acc[mt][nt], ah[mt][0], ah[mt][1], ah[mt][2], ah[mt][3],
                         bf[nt].x, bf[nt].y);
            }
        }
    }
}

#define ZACC4(acc) do { _Pragma("unroll") for (int a_ = 0; a_ < 2; a_++) \
    _Pragma("unroll") for (int b_ = 0; b_ < 4; b_++) \
    _Pragma("unroll") for (int c_ = 0; c_ < 4; c_++) acc[a_][b_][c_] = 0.0f; } while (0)
#define ZACC2(acc) do { _Pragma("unroll") for (int a_ = 0; a_ < 2; a_++) \
    _Pragma("unroll") for (int b_ = 0; b_ < 2; b_++) \
    _Pragma("unroll") for (int c_ = 0; c_ < 4; c_++) acc[a_][b_][c_] = 0.0f; } while (0)

#define SH 68
#define SHN 132

// ---------------- pre: P/Q = h @ We1 halves, 32 nodes/block ----------------
#define POFF_ALO 4224
#define POFF_MISC 8448
#define PRE_SMEM_BYTES ((POFF_MISC + 128) * 4)

__global__ void __launch_bounds__(TE, 3)
pre_mma_kernel(const float* __restrict__ h, const float* __restrict__ be1)
{
    extern __shared__ u32 smu[];
    u32* Ahi = smu;
    u32* Alo = smu + POFF_ALO;
    float* s_be1 = (float*)(smu + POFF_MISC);

    const int tid  = threadIdx.x;
    const int lane = tid & 31;
    const int wid  = tid >> 5;
    const int g    = lane >> 2;
    const int tig  = lane & 3;
    const int ntb  = wid * 2;
    const int n0   = blockIdx.x * 32;

    const u32 smb = smem_u32(smu);
    const u32 AhiA = smb;
    const u32 AloA = smb + POFF_ALO * 4;

    if (tid < 128) s_be1[tid] = be1[tid];

    for (int r = wid * 4; r < wid * 4 + 4; r++) {
        int n = n0 + r;
        float4 v = make_float4(0.f, 0.f, 0.f, 0.f);
        if (n < N_NODES) v = __ldg((const float4*)(h + (size_t)n * 128) + lane);
        u32 h0 = bf16x2_rn(v.x, v.y), h1 = bf16x2_rn(v.z, v.w);
        int o = r * SH + lane * 2;
        *(uint2*)&Ahi[o] = make_uint2(h0, h1);
        *(uint2*)&Alo[o] = make_uint2(bf16x2_lo(v.x, v.y, h0), bf16x2_lo(v.z, v.w, h1));
    }
    __syncthreads();

    float acc[2][2][4];

    ZACC2(acc);
    mma3<8, 2>(AhiA, AloA, SH, g_Bfp, acc, 0, ntb, lane);
#pragma unroll
    for (int mt = 0; mt < 2; mt++) {
        int ra = mt * 16 + g, rb = ra + 8;
        int na = n0 + ra, nb = n0 + rb;
#pragma unroll
        for (int nt = 0; nt < 2; nt++) {
            int col = (ntb + nt) * 8 + 2 * tig;
            float b0 = s_be1[col], b1 = s_be1[col + 1];
            if (na < N_NODES)
                *(float2*)&g_P[(size_t)na * 128 + col] =
                    make_float2(acc[mt][nt][0] + b0, acc[mt][nt][1] + b1);
            if (nb < N_NODES)
                *(float2*)&g_P[(size_t)nb * 128 + col] =
                    make_float2(acc[mt][nt][2] + b0, acc[mt][nt][3] + b1);
        }
    }

    ZACC2(acc);
    mma3<8, 2>(AhiA, AloA, SH, g_Bfq, acc, 0, ntb, lane);
#pragma unroll
    for (int mt = 0; mt < 2; mt++) {
        int ra = mt * 16 + g, rb = ra + 8;
        int na = n0 + ra, nb = n0 + rb;
#pragma unroll
        for (int nt = 0; nt < 2; nt++) {
            int col = (ntb + nt) * 8 + 2 * tig;
            if (na < N_NODES)
                *(float2*)&g_Q[(size_t)na * 128 + col] =
                    make_float2(acc[mt][nt][0], acc[mt][nt][1]);
            if (nb < N_NODES)
                *(float2*)&g_Q[(size_t)nb * 128 + col] =
                    make_float2(acc[mt][nt][2], acc[mt][nt][3]);
        }
    }
}

// ---------------- edge kernel: 32 edges/block, 128 threads, 7 CTAs/SM ----------------
#define OFF_EFH  2176
#define OFF_MISC 4352
#define SMEM_EDGE_U32 (OFF_MISC + 832)
#define SMEM_EDGE_BYTES (SMEM_EDGE_U32 * 4)

__global__ void __launch_bounds__(TEE, 7)
edge_kernel(const float* __restrict__ y, const int* __restrict__ ei,
            const float* __restrict__ w256,
            const float* __restrict__ be2, const float* __restrict__ bc1,
            const float* __restrict__ Wc2)
{
    extern __shared__ u32 smu[];
    u32* hidH = smu;
    u32* efH  = smu + OFF_EFH;
    float* s_w256 = (float*)(smu + OFF_MISC);
    float* s_be2  = s_w256 + 128;
    float* s_bc1  = s_be2 + 128;
    float* s_wc2  = s_bc1 + 128;
    float* s_rad  = s_wc2 + 128;   // [32]
    float* s_diff = s_rad + 32;    // [32][3]
    float* s_part = s_diff + 96;   // [4][32]
    int*   s_row  = (int*)(s_part + 128);  // [32]
    int*   s_col  = s_row + 32;            // [32]

    const int tid  = threadIdx.x;
    const int lane = tid & 31;
    const int wid  = tid >> 5;     // 0..3 = ntile group
    const int g    = lane >> 2;
    const int tig  = lane & 3;
    const int ntb  = wid * 4;
    const int e0g  = blockIdx.x * 32;

    const u32 smb   = smem_u32(smu);
    const u32 hidHa = smb;
    const u32 efHa  = smb + OFF_EFH * 4;

    if (tid < 32) {
        int r = ei[e0g + tid], c = ei[N_EDGES + e0g + tid];
        s_row[tid] = r; s_col[tid] = c;
        float dx = y[r*3+0]-y[c*3+0], dy = y[r*3+1]-y[c*3+1], dz = y[r*3+2]-y[c*3+2];
        s_diff[tid*3+0] = dx; s_diff[tid*3+1] = dy; s_diff[tid*3+2] = dz;
        s_rad[tid] = dx*dx + dy*dy + dz*dz;
    }
    if (tid < 128) {
        s_w256[tid] = w256[tid];
        s_be2[tid] = be2[tid]; s_bc1[tid] = bc1[tid]; s_wc2[tid] = Wc2[tid];
    }
    __syncthreads();

    // ---- fused former-GEMM1: hid = silu(P[row] + Q[col] + rad*w256), hi only ----
#pragma unroll 2
    for (int t = wid; t < 32; t += 4) {
        int rnode = s_row[t], cnode = s_col[t];
        float4 p = __ldg((const float4*)(g_P + (size_t)rnode * 128) + lane);
        float4 q = __ldg((const float4*)(g_Q + (size_t)cnode * 128) + lane);
        float rad = s_rad[t];
        float4 w = *(const float4*)&s_w256[lane * 4];
        float v0 = silu_f(p.x + q.x + rad * w.x);
        float v1 = silu_f(p.y + q.y + rad * w.y);
        float v2 = silu_f(p.z + q.z + rad * w.z);
        float v3 = silu_f(p.w + q.w + rad * w.w);
        int o = t * SH + lane * 2;
        *(uint2*)&hidH[o] = make_uint2(bf16x2_rn(v0, v1), bf16x2_rn(v2, v3));
    }
    __syncthreads();

    float acc[2][4][4];

    // ---- GEMM2: hid @ We2 (2-term, permuted columns) ----
    ZACC4(acc);
    mma2a<8, 4>(hidHa, SH, g_Bf2, acc, 0, ntb, lane);
#pragma unroll
    for (int mt = 0; mt < 2; mt++) {
        int ra = mt * 16 + g, rb = ra + 8;
        size_t na = (size_t)s_row[ra] * 128, nb = (size_t)s_row[rb] * 128;
#pragma unroll
        for (int j = 0; j < 2; j++) {
            int q  = wid * 2 + j;
            int cb = 16 * q + 4 * tig;
            float b0 = s_be2[cb], b1 = s_be2[cb+1], b2 = s_be2[cb+2], b3 = s_be2[cb+3];
            float* A0 = acc[mt][2*j];
            float* A1 = acc[mt][2*j + 1];
            float r0 = silu_f(A0[0] + b0), r1 = silu_f(A0[1] + b1);
            float r2 = silu_f(A1[0] + b2), r3 = silu_f(A1[1] + b3);
            float s0 = silu_f(A0[2] + b0), s1 = silu_f(A0[3] + b1);
            float s2 = silu_f(A1[2] + b2), s3 = silu_f(A1[3] + b3);
            int u = 8 * q + 2 * tig;
            *(uint2*)&efH[ra * SH + u] = make_uint2(bf16x2_rn(r0, r1), bf16x2_rn(r2, r3));
            *(uint2*)&efH[rb * SH + u] = make_uint2(bf16x2_rn(s0, s1), bf16x2_rn(s2, s3));
            red_v4(&g_hagg[na + cb], make_float4(r0, r1, r2, r3));
            red_v4(&g_hagg[nb + cb], make_float4(s0, s1, s2, s3));
        }
    }
    __syncthreads();

    // ---- GEMM3: ef @ Wc1 (1-term, coord path) ----
    ZACC4(acc);
    mma1t<8>(efHa, SH, g_Bf3, acc, 0, ntb, lane);
    {
        float p[4] = {0.f, 0.f, 0.f, 0.f};
#pragma unroll
        for (int mt = 0; mt < 2; mt++) {
#pragma unroll
            for (int nt = 0; nt < 4; nt++) {
                int col = (ntb + nt) * 8 + 2 * tig;
                float b0 = s_bc1[col], b1 = s_bc1[col + 1];
                float w0 = s_wc2[col], w1 = s_wc2[col + 1];
                p[mt*2+0] += silu_f(acc[mt][nt][0] + b0) * w0
                           + silu_f(acc[mt][nt][1] + b1) * w1;
                p[mt*2+1] += silu_f(acc[mt][nt][2] + b0) * w0
                           + silu_f(acc[mt][nt][3] + b1) * w1;
            }
        }
#pragma unroll
        for (int i = 0; i < 4; i++) {
            p[i] += __shfl_xor_sync(0xffffffffu, p[i], 1);
            p[i] += __shfl_xor_sync(0xffffffffu, p[i], 2);
        }
        if (tig == 0) {
#pragma unroll
            for (int mt = 0; mt < 2; mt++) {
                s_part[wid * 32 + mt * 16 + g]     = p[mt*2+0];
                s_part[wid * 32 + mt * 16 + g + 8] = p[mt*2+1];
            }
        }
    }
    __syncthreads();

    if (tid < 32) {
        float s = s_part[tid] + s_part[32 + tid] + s_part[64 + tid] + s_part[96 + tid];
        float4 v = make_float4(s_diff[tid*3+0] * s, s_diff[tid*3+1] * s,
                               s_diff[tid*3+2] * s, 1.0f);
        red_v4(&g_cagg4[s_row[tid] * 4], v);
    }
}

// ---------------- node kernel: 32 nodes/block, overlaid SMEM ----------------
#define NOFF_ALO 4224
#define NOFF_HL  2176
#define NOFF_MISC 8448
#define SMEM_NODE_BYTES ((NOFF_MISC + 256) * 4)

__global__ void __launch_bounds__(TE, 3)
node_mma_kernel(const float* __restrict__ h, const float* __restrict__ y,
                const float* __restrict__ bn1, const float* __restrict__ bn2,
                float* __restrict__ out_h, float* __restrict__ out_y)
{
    extern __shared__ u32 smu[];
    u32* AhiN = smu;
    u32* AloN = smu + NOFF_ALO;
    u32* hidH = smu;
    u32* hidL = smu + NOFF_HL;
    float* s_bn1 = (float*)(smu + NOFF_MISC);
    float* s_bn2 = s_bn1 + 128;

    const int tid  = threadIdx.x;
    const int lane = tid & 31;
    const int wid  = tid >> 5;
    const int g    = lane >> 2;
    const int tig  = lane & 3;
    const int ntb  = wid * 2;
    const int n0   = blockIdx.x * 32;

    const u32 smb = smem_u32(smu);
    const u32 AhiA = smb;
    const u32 AloA = smb + NOFF_ALO * 4;
    const u32 hHa  = smb;
    const u32 hLa  = smb + NOFF_HL * 4;

    if (tid < 128) { s_bn1[tid] = bn1[tid]; s_bn2[tid] = bn2[tid]; }

    for (int t = wid; t < 64; t += 8) {
        int r = t >> 1, half = t & 1, n = n0 + r;
        float4 v = make_float4(0.f, 0.f, 0.f, 0.f);
        if (n < N_NODES) {
            const float* src = half ? (g_hagg + (size_t)n * 128) : (h + (size_t)n * 128);
            v = __ldg((const float4*)src + lane);
        }
        u32 h0 = bf16x2_rn(v.x, v.y), h1 = bf16x2_rn(v.z, v.w);
        int o = r * SHN + half * 64 + lane * 2;
        *(uint2*)&AhiN[o] = make_uint2(h0, h1);
        *(uint2*)&AloN[o] = make_uint2(bf16x2_lo(v.x, v.y, h0), bf16x2_lo(v.z, v.w, h1));
    }
    __syncthreads();

    float acc[2][2][4];

    ZACC2(acc);
    mma3<16, 2>(AhiA, AloA, SHN, g_Bfn1, acc, 0, ntb, lane);
    __syncthreads();
#pragma unroll
    for (int mt = 0; mt < 2; mt++) {
        int ra = mt * 16 + g, rb = ra + 8;
#pragma unroll
        for (int nt = 0; nt < 2; nt++) {
            int col = (ntb + nt) * 8 + 2 * tig;
            int uc  = (ntb + nt) * 4 + tig;
            float b0 = s_bn1[col], b1 = s_bn1[col + 1];
            float v0 = silu_f(acc[mt][nt][0] + b0), v1 = silu_f(acc[mt][nt][1] + b1);
            float v2 = silu_f(acc[mt][nt][2] + b0), v3 = silu_f(acc[mt][nt][3] + b1);
            u32 ha = bf16x2_rn(v0, v1), hb = bf16x2_rn(v2, v3);
            hidH[ra * SH + uc] = ha; hidL[ra * SH + uc] = bf16x2_lo(v0, v1, ha);
            hidH[rb * SH + uc] = hb; hidL[rb * SH + uc] = bf16x2_lo(v2, v3, hb);
        }
    }
    __syncthreads();

    ZACC2(acc);
    mma3<8, 2>(hHa, hLa, SH, g_Bfn2, acc, 0, ntb, lane);
#pragma unroll
    for (int mt = 0; mt < 2; mt++) {
        int ra = mt * 16 + g, rb = ra + 8;
        int na = n0 + ra, nb = n0 + rb;
#pragma unroll
        for (int nt = 0; nt < 2; nt++) {
            int col = (ntb + nt) * 8 + 2 * tig;
            float b0 = s_bn2[col], b1 = s_bn2[col + 1];
            if (na < N_NODES) {
                float2 hh = __ldg((const float2*)(h + (size_t)na * 128 + col));
                *(float2*)&out_h[(size_t)na * 128 + col] =
                    make_float2(acc[mt][nt][0] + b0 + hh.x, acc[mt][nt][1] + b1 + hh.y);
            }
            if (nb < N_NODES) {
                float2 hh = __ldg((const float2*)(h + (size_t)nb * 128 + col));
                *(float2*)&out_h[(size_t)nb * 128 + col] =
                    make_float2(acc[mt][nt][2] + b0 + hh.x, acc[mt][nt][3] + b1 + hh.y);
            }
        }
    }

    if (tid < 32) {
        int n = n0 + tid;
        if (n < N_NODES) {
            float c = g_cagg4[n * 4 + 3]; c = (c < 1.0f) ? 1.0f : c;
            out_y[n*3+0] = y[n*3+0] + g_cagg4[n*4+0] / c;
            out_y[n*3+1] = y[n*3+1] + g_cagg4[n*4+1] / c;
            out_y[n*3+2] = y[n*3+2] + g_cagg4[n*4+2] / c;
        }
    }
}

extern "C" void kernel_launch(void* const* d_in, const int* in_sizes, int n_in,
                              void* d_out, int out_size)
{
    const float* h   = (const float*)d_in[0];
    const float* y   = (const float*)d_in[1];
    const int*   ei  = (const int*)d_in[2];
    const float* We1 = (const float*)d_in[3];
    const float* be1 = (const float*)d_in[4];
    const float* We2 = (const float*)d_in[5];
    const float* be2 = (const float*)d_in[6];
    const float* Wc1 = (const float*)d_in[7];
    const float* bc1 = (const float*)d_in[8];
    const float* Wc2 = (const float*)d_in[9];
    const float* Wn1 = (const float*)d_in[10];
    const float* bn1 = (const float*)d_in[11];
    const float* Wn2 = (const float*)d_in[12];
    const float* bn2 = (const float*)d_in[13];

    float* out_h = (float*)d_out;
    float* out_y = out_h + (size_t)N_NODES * 128;

    cudaFuncSetAttribute(edge_kernel, cudaFuncAttributeMaxDynamicSharedMemorySize,
                         SMEM_EDGE_BYTES);
    cudaFuncSetAttribute(node_mma_kernel, cudaFuncAttributeMaxDynamicSharedMemorySize,
                         SMEM_NODE_BYTES);
    cudaFuncSetAttribute(pre_mma_kernel, cudaFuncAttributeMaxDynamicSharedMemorySize,
                         PRE_SMEM_BYTES);

    zp_kernel<<<624, TE>>>(We1, We2, Wc1, Wn1, Wn2);
    pre_mma_kernel<<<(N_NODES + 31) / 32, TE, PRE_SMEM_BYTES>>>(h, be1);

    edge_kernel<<<N_EDGES / 32, TEE, SMEM_EDGE_BYTES>>>(
        y, ei, We1 + 256 * 128, be2, bc1, Wc2);

    node_mma_kernel<<<(N_NODES + 31) / 32, TE, SMEM_NODE_BYTES>>>(
        h, y, bn1, bn2, out_h, out_y);
}